// round 1
// baseline (speedup 1.0000x reference)
#include <cuda_runtime.h>
#include <math.h>

// Problem constants
#define BATCH   16
#define SEQ     512
#define DMODEL  1024
#define NHEAD   16
#define HDIM    64
#define ROWS    (BATCH * SEQ)          // 8192
#define WIN     64                     // WINDOW/2
#define SCALE   0.125f                 // 64^-0.5

// ---------------------------------------------------------------------------
// Scratch (device globals: allocation-free workaround per harness rules)
// ---------------------------------------------------------------------------
__device__ float g_q   [ROWS * DMODEL];
__device__ float g_k   [ROWS * DMODEL];
__device__ float g_v   [ROWS * DMODEL];
__device__ float g_g   [ROWS * DMODEL];
__device__ float g_attn[ROWS * DMODEL];
__device__ float g_proj[ROWS * DMODEL];

// ---------------------------------------------------------------------------
// SGEMM (NT): C[M,N] = A[M,K] * W[N,K]^T + bias[N]
// BM=BN=128, BK=16, 256 threads, 8x8 register tile per thread.
// M=8192, N=1024, K=1024 -> no bounds checks needed (all divisible).
// ---------------------------------------------------------------------------
#define BM 128
#define BN 128
#define BK 16
#define TM 8
#define TN 8

__global__ __launch_bounds__(256) void sgemm_nt_bias(
    const float* __restrict__ A,     // [M,K]
    const float* __restrict__ W,     // [N,K]
    const float* __restrict__ bias,  // [N]
    float* __restrict__ C,           // [M,N]
    int M, int N, int K)
{
    __shared__ float As[BK][BM];
    __shared__ float Ws[BK][BN];

    const int t  = threadIdx.x;
    const int tx = t & 15;           // 0..15
    const int ty = t >> 4;           // 0..15
    const int bm = blockIdx.y * BM;
    const int bn = blockIdx.x * BN;

    float acc[TM][TN];
    #pragma unroll
    for (int i = 0; i < TM; i++)
        #pragma unroll
        for (int j = 0; j < TN; j++)
            acc[i][j] = 0.0f;

    const float* Ablk = A + (size_t)bm * K;
    const float* Wblk = W + (size_t)bn * K;

    for (int k0 = 0; k0 < K; k0 += BK) {
        // 128 rows x 16 cols = 512 float4 per tile; 2 per thread (A and W each)
        #pragma unroll
        for (int i = 0; i < 2; i++) {
            int idx = t + i * 256;          // 0..511
            int row = idx >> 2;             // 0..127
            int c4  = (idx & 3) << 2;       // {0,4,8,12}
            float4 va = *(const float4*)&Ablk[(size_t)row * K + k0 + c4];
            As[c4 + 0][row] = va.x;
            As[c4 + 1][row] = va.y;
            As[c4 + 2][row] = va.z;
            As[c4 + 3][row] = va.w;
            float4 vw = *(const float4*)&Wblk[(size_t)row * K + k0 + c4];
            Ws[c4 + 0][row] = vw.x;
            Ws[c4 + 1][row] = vw.y;
            Ws[c4 + 2][row] = vw.z;
            Ws[c4 + 3][row] = vw.w;
        }
        __syncthreads();

        #pragma unroll
        for (int kk = 0; kk < BK; kk++) {
            float a[TM], b[TN];
            #pragma unroll
            for (int i = 0; i < TM; i++) a[i] = As[kk][ty * TM + i];
            #pragma unroll
            for (int j = 0; j < TN; j++) b[j] = Ws[kk][tx * TN + j];
            #pragma unroll
            for (int i = 0; i < TM; i++)
                #pragma unroll
                for (int j = 0; j < TN; j++)
                    acc[i][j] += a[i] * b[j];
        }
        __syncthreads();
    }

    #pragma unroll
    for (int i = 0; i < TM; i++) {
        int m = bm + ty * TM + i;
        #pragma unroll
        for (int j = 0; j < TN; j += 4) {
            int n = bn + tx * TN + j;
            float4 v;
            v.x = acc[i][j + 0] + bias[n + 0];
            v.y = acc[i][j + 1] + bias[n + 1];
            v.z = acc[i][j + 2] + bias[n + 2];
            v.w = acc[i][j + 3] + bias[n + 3];
            *(float4*)&C[(size_t)m * N + n] = v;
        }
    }
}

// ---------------------------------------------------------------------------
// Windowed attention: per (b, h, 64-query tile).
// Keys needed for q-tile [q0, q0+63]: [q0-64, q0+127] -> 192 rows in smem.
// 8 warps, each warp processes queries q0+w, q0+w+8, ... (8 per warp).
// ---------------------------------------------------------------------------
#define KRANGE 192
#define KPAD   65   // 65 mod 32 = 1 -> conflict-free K reads in QK loop

__global__ __launch_bounds__(256) void attn_win(
    const float* __restrict__ Q,
    const float* __restrict__ K,
    const float* __restrict__ V,
    float* __restrict__ O)
{
    extern __shared__ float sm[];
    float* Ks = sm;                          // [192][65]
    float* Vs = Ks + KRANGE * KPAD;          // [192][64]
    float* Qs = Vs + KRANGE * HDIM;          // [64][64]
    float* Ps = Qs + 64 * HDIM;              // [8][192]

    const int qt   = blockIdx.x;             // 0..7
    const int h    = blockIdx.y;             // 0..15
    const int b    = blockIdx.z;             // 0..15
    const int t    = threadIdx.x;
    const int lane = t & 31;
    const int w    = t >> 5;

    const int q0    = qt * 64;
    const int kbase = q0 - WIN;              // may be negative

    const float* Qbh = Q + ((size_t)b * SEQ) * DMODEL + h * HDIM;
    const float* Kbh = K + ((size_t)b * SEQ) * DMODEL + h * HDIM;
    const float* Vbh = V + ((size_t)b * SEQ) * DMODEL + h * HDIM;

    // Stage K and V (zero-fill out of range)
    for (int idx = t; idx < KRANGE * HDIM; idx += 256) {
        int j = idx >> 6, d = idx & 63;
        int jg = kbase + j;
        float kv = 0.0f, vv = 0.0f;
        if (jg >= 0 && jg < SEQ) {
            kv = Kbh[(size_t)jg * DMODEL + d];
            vv = Vbh[(size_t)jg * DMODEL + d];
        }
        Ks[j * KPAD + d] = kv;
        Vs[j * HDIM + d] = vv;
    }
    // Stage Q
    for (int idx = t; idx < 64 * HDIM; idx += 256) {
        int q = idx >> 6, d = idx & 63;
        Qs[q * HDIM + d] = Qbh[(size_t)(q0 + q) * DMODEL + d];
    }
    __syncthreads();

    for (int q = w; q < 64; q += 8) {
        const int qi = q0 + q;
        const float* qr = &Qs[q * HDIM];

        float s[6];
        #pragma unroll
        for (int r = 0; r < 6; r++) {
            int j  = r * 32 + lane;
            int jg = kbase + j;
            int dq = qi - jg;
            bool valid = (jg >= 0) && (jg < SEQ) && (dq <= WIN) && (dq >= -WIN);
            float acc = 0.0f;
            const float* kr = &Ks[j * KPAD];
            #pragma unroll
            for (int d = 0; d < HDIM; d++) acc += qr[d] * kr[d];
            s[r] = valid ? acc * SCALE : -1e30f;
        }

        // softmax over the 192 slots (invalid -> ~0 after exp)
        float m = s[0];
        #pragma unroll
        for (int r = 1; r < 6; r++) m = fmaxf(m, s[r]);
        #pragma unroll
        for (int o = 16; o > 0; o >>= 1) m = fmaxf(m, __shfl_xor_sync(0xffffffffu, m, o));
        float sum = 0.0f;
        #pragma unroll
        for (int r = 0; r < 6; r++) { s[r] = __expf(s[r] - m); sum += s[r]; }
        #pragma unroll
        for (int o = 16; o > 0; o >>= 1) sum += __shfl_xor_sync(0xffffffffu, sum, o);
        float inv = 1.0f / sum;
        #pragma unroll
        for (int r = 0; r < 6; r++) Ps[w * KRANGE + r * 32 + lane] = s[r] * inv;
        __syncwarp();

        // PV: lane owns output dims {lane, lane+32}
        float o0 = 0.0f, o1 = 0.0f;
        const float* pw = &Ps[w * KRANGE];
        #pragma unroll 4
        for (int j = 0; j < KRANGE; j++) {
            float p = pw[j];
            o0 += p * Vs[j * HDIM + lane];
            o1 += p * Vs[j * HDIM + lane + 32];
        }
        float* orow = O + ((size_t)b * SEQ + qi) * DMODEL + h * HDIM;
        orow[lane]      = o0;
        orow[lane + 32] = o1;
        __syncwarp();
    }
}

// ---------------------------------------------------------------------------
// Fused epilogue: gate = sigmoid(gpre); y = 0.5*x + 0.5*gate*proj; LayerNorm
// One CTA of 256 threads per row (1024 elems -> 4 per thread).
// ---------------------------------------------------------------------------
__global__ __launch_bounds__(256) void fused_epilogue(
    const float* __restrict__ X,
    const float* __restrict__ Gpre,
    const float* __restrict__ Pr,
    const float* __restrict__ gamma,
    const float* __restrict__ beta,
    float* __restrict__ out)
{
    const int r = blockIdx.x;
    const int t = threadIdx.x;
    const float* x = X    + (size_t)r * DMODEL;
    const float* g = Gpre + (size_t)r * DMODEL;
    const float* p = Pr   + (size_t)r * DMODEL;

    float y[4];
    float lsum = 0.0f, lsq = 0.0f;
    #pragma unroll
    for (int i = 0; i < 4; i++) {
        int c = t + i * 256;
        float gate = 1.0f / (1.0f + __expf(-g[c]));
        float v = 0.5f * x[c] + 0.5f * gate * p[c];
        y[i] = v;
        lsum += v;
        lsq  += v * v;
    }

    #pragma unroll
    for (int o = 16; o > 0; o >>= 1) {
        lsum += __shfl_xor_sync(0xffffffffu, lsum, o);
        lsq  += __shfl_xor_sync(0xffffffffu, lsq, o);
    }
    __shared__ float red[2][8];
    const int w = t >> 5, lane = t & 31;
    if (lane == 0) { red[0][w] = lsum; red[1][w] = lsq; }
    __syncthreads();
    float tsum = 0.0f, tsq = 0.0f;
    #pragma unroll
    for (int i = 0; i < 8; i++) { tsum += red[0][i]; tsq += red[1][i]; }

    const float mean = tsum * (1.0f / DMODEL);
    const float var  = tsq * (1.0f / DMODEL) - mean * mean;
    const float rstd = rsqrtf(var + 1e-5f);

    float* o = out + (size_t)r * DMODEL;
    #pragma unroll
    for (int i = 0; i < 4; i++) {
        int c = t + i * 256;
        o[c] = (y[i] - mean) * rstd * gamma[c] + beta[c];
    }
}

// ---------------------------------------------------------------------------
// Launch
// ---------------------------------------------------------------------------
extern "C" void kernel_launch(void* const* d_in, const int* in_sizes, int n_in,
                              void* d_out, int out_size)
{
    const float* X     = (const float*)d_in[0];   // hidden_states
    const float* Cx    = (const float*)d_in[1];   // cross_states
    const float* Wq    = (const float*)d_in[2];
    const float* bq    = (const float*)d_in[3];
    const float* Wk    = (const float*)d_in[4];
    const float* bk    = (const float*)d_in[5];
    const float* Wv    = (const float*)d_in[6];
    const float* bv    = (const float*)d_in[7];
    const float* Wo    = (const float*)d_in[8];
    const float* bo    = (const float*)d_in[9];
    const float* Wg    = (const float*)d_in[10];
    const float* bg    = (const float*)d_in[11];
    const float* gamma = (const float*)d_in[12];
    const float* beta  = (const float*)d_in[13];
    float* out = (float*)d_out;

    float *q, *k, *v, *g, *attn, *proj;
    cudaGetSymbolAddress((void**)&q,    g_q);
    cudaGetSymbolAddress((void**)&k,    g_k);
    cudaGetSymbolAddress((void**)&v,    g_v);
    cudaGetSymbolAddress((void**)&g,    g_g);
    cudaGetSymbolAddress((void**)&attn, g_attn);
    cudaGetSymbolAddress((void**)&proj, g_proj);

    const int attn_smem = (KRANGE * KPAD + KRANGE * HDIM + 64 * HDIM + 8 * KRANGE) * sizeof(float);
    cudaFuncSetAttribute(attn_win, cudaFuncAttributeMaxDynamicSharedMemorySize, attn_smem);

    dim3 gemm_grid(DMODEL / BN, ROWS / BM);   // (8, 64)
    dim3 gemm_blk(256);

    // Projections from hidden_states
    sgemm_nt_bias<<<gemm_grid, gemm_blk>>>(X,  Wq, bq, q, ROWS, DMODEL, DMODEL);
    sgemm_nt_bias<<<gemm_grid, gemm_blk>>>(X,  Wg, bg, g, ROWS, DMODEL, DMODEL);
    // Projections from cross_states
    sgemm_nt_bias<<<gemm_grid, gemm_blk>>>(Cx, Wk, bk, k, ROWS, DMODEL, DMODEL);
    sgemm_nt_bias<<<gemm_grid, gemm_blk>>>(Cx, Wv, bv, v, ROWS, DMODEL, DMODEL);

    // Windowed attention
    dim3 attn_grid(SEQ / 64, NHEAD, BATCH);   // (8, 16, 16)
    attn_win<<<attn_grid, 256, attn_smem>>>(q, k, v, attn);

    // Output projection
    sgemm_nt_bias<<<gemm_grid, gemm_blk>>>(attn, Wo, bo, proj, ROWS, DMODEL, DMODEL);

    // Gate + blend + LayerNorm
    fused_epilogue<<<ROWS, 256>>>(X, g, proj, gamma, beta, out);
}

// round 4
// speedup vs baseline: 2.2902x; 2.2902x over previous
#include <cuda_runtime.h>
#include <math.h>
#include <stdint.h>

// Problem constants
#define BATCH   16
#define SEQ     512
#define DMODEL  1024
#define NHEAD   16
#define HDIM    64
#define ROWS    (BATCH * SEQ)          // 8192
#define WIN     64                     // WINDOW/2
#define SCALE   0.125f                 // 64^-0.5

// ---------------------------------------------------------------------------
// Scratch (device globals: allocation-free workaround per harness rules)
// ---------------------------------------------------------------------------
__device__ float g_q   [ROWS * DMODEL];
__device__ float g_k   [ROWS * DMODEL];
__device__ float g_v   [ROWS * DMODEL];
__device__ float g_g   [ROWS * DMODEL];
__device__ float g_attn[ROWS * DMODEL];
__device__ float g_proj[ROWS * DMODEL];
// tf32-rounded copies (feeds for tensor-core GEMMs)
__device__ float g_xr  [ROWS * DMODEL];
__device__ float g_cxr [ROWS * DMODEL];
__device__ float g_wqr [DMODEL * DMODEL];
__device__ float g_wkr [DMODEL * DMODEL];
__device__ float g_wvr [DMODEL * DMODEL];
__device__ float g_wgr [DMODEL * DMODEL];
__device__ float g_wor [DMODEL * DMODEL];

// ---------------------------------------------------------------------------
// Helpers
// ---------------------------------------------------------------------------
__device__ __forceinline__ uint32_t smem_u32(const void* p) {
    uint32_t a;
    asm("{ .reg .u64 t; cvta.to.shared.u64 t, %1; cvt.u32.u64 %0, t; }"
        : "=r"(a) : "l"(p));
    return a;
}

__device__ __forceinline__ uint32_t lds32(uint32_t addr) {
    uint32_t v;
    asm volatile("ld.shared.b32 %0, [%1];" : "=r"(v) : "r"(addr));
    return v;
}

// ---------------------------------------------------------------------------
// tf32 rounding prep kernel (cvt.rna kills truncation bias)
// ---------------------------------------------------------------------------
__global__ __launch_bounds__(256) void tf32_round_kernel(
    const float4* __restrict__ in, float4* __restrict__ out, int n4)
{
    int i = blockIdx.x * 256 + threadIdx.x;
    if (i < n4) {
        float4 v = in[i];
        uint32_t a, b, c, d;
        asm("cvt.rna.tf32.f32 %0, %1;" : "=r"(a) : "f"(v.x));
        asm("cvt.rna.tf32.f32 %0, %1;" : "=r"(b) : "f"(v.y));
        asm("cvt.rna.tf32.f32 %0, %1;" : "=r"(c) : "f"(v.z));
        asm("cvt.rna.tf32.f32 %0, %1;" : "=r"(d) : "f"(v.w));
        out[i] = make_float4(__uint_as_float(a), __uint_as_float(b),
                             __uint_as_float(c), __uint_as_float(d));
    }
}

// ---------------------------------------------------------------------------
// tf32 mma.sync GEMM: C[M,N] = A[M,K] * W[N,K]^T + bias[N]
// CTA 128x128, BK=32, 256 threads (8 warps, 2x4), warp tile 64x32.
// 4-stage cp.async pipeline. Smem rows = 128B with chunk-XOR swizzle:
//   float offset (row, k): row*32 + ((chunk ^ (row&7))*4) + (k&3), chunk=k>>2
// All mma fragment rows satisfy row%8 == g (lane>>2), so fragment LDS.32
// loads are conflict-free and the swizzle selector is just g.
// ---------------------------------------------------------------------------
#define GBM 128
#define GBN 128
#define GBK 32
#define GSTAGES 4
#define GITERS (DMODEL / GBK)                  // 32
#define TILE_BYTES  (GBM * GBK * 4)            // 16384 (each of A, B)
#define STAGE_BYTES (2 * TILE_BYTES)           // 32768
#define GEMM_SMEM   (GSTAGES * STAGE_BYTES)    // 131072

__device__ __forceinline__ void cp_stage(uint32_t sA, uint32_t sB,
                                         const float* __restrict__ Arow,
                                         const float* __restrict__ Wrow,
                                         int k0, int t)
{
    #pragma unroll
    for (int i = 0; i < 4; i++) {
        int idx = i * 256 + t;                    // 0..1023
        int row = idx >> 3;                       // 0..127
        int c   = idx & 7;                        // 16B chunk in 128B row
        uint32_t soff = (uint32_t)(row * 128 + ((c ^ (row & 7)) << 4));
        const float* ga = Arow + (size_t)row * DMODEL + k0 + c * 4;
        const float* gb = Wrow + (size_t)row * DMODEL + k0 + c * 4;
        asm volatile("cp.async.cg.shared.global [%0], [%1], 16;" :: "r"(sA + soff), "l"(ga));
        asm volatile("cp.async.cg.shared.global [%0], [%1], 16;" :: "r"(sB + soff), "l"(gb));
    }
}

__global__ __launch_bounds__(256, 1)
void gemm_mma(const float* __restrict__ A,     // [8192,1024] tf32-rounded
              const float* __restrict__ W,     // [1024,1024] tf32-rounded
              const float* __restrict__ bias,  // [1024] fp32
              float* __restrict__ C)           // [8192,1024]
{
    extern __shared__ char smem[];
    const uint32_t sb = smem_u32(smem);
    const int t = threadIdx.x;
    const int bm = blockIdx.y * GBM;
    const int bn = blockIdx.x * GBN;

    const int lane = t & 31;
    const int warp = t >> 5;
    const int g    = lane >> 2;        // 0..7
    const int tig  = lane & 3;         // 0..3
    const int wm   = warp >> 2;        // 0..1
    const int wn   = warp & 3;         // 0..3
    const int m_base = wm * 64;
    const int n_base = wn * 32;

    const float* Arow = A + (size_t)bm * DMODEL;
    const float* Wrow = W + (size_t)bn * DMODEL;

    // Precomputed fragment row byte-offsets (within a stage tile)
    uint32_t aRow[8];   // [fi*2 + h], h=0: rows g, h=1: rows g+8
    #pragma unroll
    for (int fi = 0; fi < 4; fi++) {
        #pragma unroll
        for (int h = 0; h < 2; h++)
            aRow[fi * 2 + h] = (uint32_t)((m_base + fi * 16 + h * 8 + g) * 128 + tig * 4);
    }
    uint32_t bRow[4];
    #pragma unroll
    for (int fj = 0; fj < 4; fj++)
        bRow[fj] = (uint32_t)((n_base + fj * 8 + g) * 128 + tig * 4);

    float acc[4][4][4];
    #pragma unroll
    for (int fi = 0; fi < 4; fi++)
        #pragma unroll
        for (int fj = 0; fj < 4; fj++)
            #pragma unroll
            for (int r = 0; r < 4; r++)
                acc[fi][fj][r] = 0.0f;

    // Prologue: prefetch first GSTAGES-1 stages
    #pragma unroll
    for (int s = 0; s < GSTAGES - 1; s++) {
        cp_stage(sb + s * STAGE_BYTES, sb + s * STAGE_BYTES + TILE_BYTES,
                 Arow, Wrow, s * GBK, t);
        asm volatile("cp.async.commit_group;" ::: "memory");
    }

    for (int it = 0; it < GITERS; it++) {
        asm volatile("cp.async.wait_group 2;" ::: "memory");
        __syncthreads();

        // Issue next stage copy (always commit — keeps wait_group count sound)
        const int ps = it + GSTAGES - 1;
        if (ps < GITERS) {
            const int s = ps % GSTAGES;
            cp_stage(sb + s * STAGE_BYTES, sb + s * STAGE_BYTES + TILE_BYTES,
                     Arow, Wrow, ps * GBK, t);
        }
        asm volatile("cp.async.commit_group;" ::: "memory");

        // Compute current stage
        const uint32_t sA = sb + (it % GSTAGES) * STAGE_BYTES;
        const uint32_t sB = sA + TILE_BYTES;

        #pragma unroll
        for (int ks = 0; ks < 4; ks++) {
            const uint32_t co0 = (uint32_t)(((2 * ks)     ^ g) << 4);
            const uint32_t co1 = (uint32_t)(((2 * ks + 1) ^ g) << 4);

            uint32_t a[4][4];
            #pragma unroll
            for (int fi = 0; fi < 4; fi++) {
                a[fi][0] = lds32(sA + aRow[fi * 2 + 0] + co0);
                a[fi][1] = lds32(sA + aRow[fi * 2 + 1] + co0);
                a[fi][2] = lds32(sA + aRow[fi * 2 + 0] + co1);
                a[fi][3] = lds32(sA + aRow[fi * 2 + 1] + co1);
            }
            uint32_t b[4][2];
            #pragma unroll
            for (int fj = 0; fj < 4; fj++) {
                b[fj][0] = lds32(sB + bRow[fj] + co0);
                b[fj][1] = lds32(sB + bRow[fj] + co1);
            }
            #pragma unroll
            for (int fi = 0; fi < 4; fi++)
                #pragma unroll
                for (int fj = 0; fj < 4; fj++) {
                    asm volatile(
                        "mma.sync.aligned.m16n8k8.row.col.f32.tf32.tf32.f32 "
                        "{%0,%1,%2,%3}, {%4,%5,%6,%7}, {%8,%9}, {%0,%1,%2,%3};"
                        : "+f"(acc[fi][fj][0]), "+f"(acc[fi][fj][1]),
                          "+f"(acc[fi][fj][2]), "+f"(acc[fi][fj][3])
                        : "r"(a[fi][0]), "r"(a[fi][1]), "r"(a[fi][2]), "r"(a[fi][3]),
                          "r"(b[fj][0]), "r"(b[fj][1]));
                }
        }
    }

    // Epilogue: bias + store (c0,c1)->(m, n..n+1), (c2,c3)->(m+8, n..n+1)
    #pragma unroll
    for (int fi = 0; fi < 4; fi++) {
        const int m0 = bm + m_base + fi * 16 + g;
        #pragma unroll
        for (int fj = 0; fj < 4; fj++) {
            const int n = bn + n_base + fj * 8 + tig * 2;
            const float2 bv = *(const float2*)&bias[n];
            float2 v0, v1;
            v0.x = acc[fi][fj][0] + bv.x;
            v0.y = acc[fi][fj][1] + bv.y;
            v1.x = acc[fi][fj][2] + bv.x;
            v1.y = acc[fi][fj][3] + bv.y;
            *(float2*)&C[(size_t)m0 * DMODEL + n]       = v0;
            *(float2*)&C[(size_t)(m0 + 8) * DMODEL + n] = v1;
        }
    }
}

// ---------------------------------------------------------------------------
// Windowed attention (R1-proven; output tf32-rounded for O-proj feed)
// ---------------------------------------------------------------------------
#define KRANGE 192
#define KPAD   65

__global__ __launch_bounds__(256) void attn_win(
    const float* __restrict__ Q,
    const float* __restrict__ K,
    const float* __restrict__ V,
    float* __restrict__ O)
{
    extern __shared__ float sm[];
    float* Ks = sm;                          // [192][65]
    float* Vs = Ks + KRANGE * KPAD;          // [192][64]
    float* Qs = Vs + KRANGE * HDIM;          // [64][64]
    float* Ps = Qs + 64 * HDIM;              // [8][192]

    const int qt   = blockIdx.x;
    const int h    = blockIdx.y;
    const int b    = blockIdx.z;
    const int t    = threadIdx.x;
    const int lane = t & 31;
    const int w    = t >> 5;

    const int q0    = qt * 64;
    const int kbase = q0 - WIN;

    const float* Qbh = Q + ((size_t)b * SEQ) * DMODEL + h * HDIM;
    const float* Kbh = K + ((size_t)b * SEQ) * DMODEL + h * HDIM;
    const float* Vbh = V + ((size_t)b * SEQ) * DMODEL + h * HDIM;

    for (int idx = t; idx < KRANGE * HDIM; idx += 256) {
        int j = idx >> 6, d = idx & 63;
        int jg = kbase + j;
        float kv = 0.0f, vv = 0.0f;
        if (jg >= 0 && jg < SEQ) {
            kv = Kbh[(size_t)jg * DMODEL + d];
            vv = Vbh[(size_t)jg * DMODEL + d];
        }
        Ks[j * KPAD + d] = kv;
        Vs[j * HDIM + d] = vv;
    }
    for (int idx = t; idx < 64 * HDIM; idx += 256) {
        int q = idx >> 6, d = idx & 63;
        Qs[q * HDIM + d] = Qbh[(size_t)(q0 + q) * DMODEL + d];
    }
    __syncthreads();

    for (int q = w; q < 64; q += 8) {
        const int qi = q0 + q;
        const float* qr = &Qs[q * HDIM];

        float s[6];
        #pragma unroll
        for (int r = 0; r < 6; r++) {
            int j  = r * 32 + lane;
            int jg = kbase + j;
            int dq = qi - jg;
            bool valid = (jg >= 0) && (jg < SEQ) && (dq <= WIN) && (dq >= -WIN);
            float acc = 0.0f;
            const float* kr = &Ks[j * KPAD];
            #pragma unroll
            for (int d = 0; d < HDIM; d++) acc += qr[d] * kr[d];
            s[r] = valid ? acc * SCALE : -1e30f;
        }

        float m = s[0];
        #pragma unroll
        for (int r = 1; r < 6; r++) m = fmaxf(m, s[r]);
        #pragma unroll
        for (int o = 16; o > 0; o >>= 1) m = fmaxf(m, __shfl_xor_sync(0xffffffffu, m, o));
        float sum = 0.0f;
        #pragma unroll
        for (int r = 0; r < 6; r++) { s[r] = __expf(s[r] - m); sum += s[r]; }
        #pragma unroll
        for (int o = 16; o > 0; o >>= 1) sum += __shfl_xor_sync(0xffffffffu, sum, o);
        float inv = 1.0f / sum;
        #pragma unroll
        for (int r = 0; r < 6; r++) Ps[w * KRANGE + r * 32 + lane] = s[r] * inv;
        __syncwarp();

        float o0 = 0.0f, o1 = 0.0f;
        const float* pw = &Ps[w * KRANGE];
        #pragma unroll 4
        for (int j = 0; j < KRANGE; j++) {
            float p = pw[j];
            o0 += p * Vs[j * HDIM + lane];
            o1 += p * Vs[j * HDIM + lane + 32];
        }
        float* orow = O + ((size_t)b * SEQ + qi) * DMODEL + h * HDIM;
        uint32_t u0, u1;   // tf32-round for downstream tensor-core O-proj
        asm("cvt.rna.tf32.f32 %0, %1;" : "=r"(u0) : "f"(o0));
        asm("cvt.rna.tf32.f32 %0, %1;" : "=r"(u1) : "f"(o1));
        orow[lane]      = __uint_as_float(u0);
        orow[lane + 32] = __uint_as_float(u1);
        __syncwarp();
    }
}

// ---------------------------------------------------------------------------
// Fused epilogue: gate = sigmoid(gpre); y = 0.5*x + 0.5*gate*proj; LayerNorm
// ---------------------------------------------------------------------------
__global__ __launch_bounds__(256) void fused_epilogue(
    const float* __restrict__ X,
    const float* __restrict__ Gpre,
    const float* __restrict__ Pr,
    const float* __restrict__ gamma,
    const float* __restrict__ beta,
    float* __restrict__ out)
{
    const int r = blockIdx.x;
    const int t = threadIdx.x;
    const float* x = X    + (size_t)r * DMODEL;
    const float* g = Gpre + (size_t)r * DMODEL;
    const float* p = Pr   + (size_t)r * DMODEL;

    float y[4];
    float lsum = 0.0f, lsq = 0.0f;
    #pragma unroll
    for (int i = 0; i < 4; i++) {
        int c = t + i * 256;
        float gate = 1.0f / (1.0f + __expf(-g[c]));
        float v = 0.5f * x[c] + 0.5f * gate * p[c];
        y[i] = v;
        lsum += v;
        lsq  += v * v;
    }

    #pragma unroll
    for (int o = 16; o > 0; o >>= 1) {
        lsum += __shfl_xor_sync(0xffffffffu, lsum, o);
        lsq  += __shfl_xor_sync(0xffffffffu, lsq, o);
    }
    __shared__ float red[2][8];
    const int w = t >> 5, lane = t & 31;
    if (lane == 0) { red[0][w] = lsum; red[1][w] = lsq; }
    __syncthreads();
    float tsum = 0.0f, tsq = 0.0f;
    #pragma unroll
    for (int i = 0; i < 8; i++) { tsum += red[0][i]; tsq += red[1][i]; }

    const float mean = tsum * (1.0f / DMODEL);
    const float var  = tsq * (1.0f / DMODEL) - mean * mean;
    const float rstd = rsqrtf(var + 1e-5f);

    float* o = out + (size_t)r * DMODEL;
    #pragma unroll
    for (int i = 0; i < 4; i++) {
        int c = t + i * 256;
        o[c] = (y[i] - mean) * rstd * gamma[c] + beta[c];
    }
}

// ---------------------------------------------------------------------------
// Launch
// ---------------------------------------------------------------------------
extern "C" void kernel_launch(void* const* d_in, const int* in_sizes, int n_in,
                              void* d_out, int out_size)
{
    const float* X     = (const float*)d_in[0];
    const float* Cx    = (const float*)d_in[1];
    const float* Wq    = (const float*)d_in[2];
    const float* bq    = (const float*)d_in[3];
    const float* Wk    = (const float*)d_in[4];
    const float* bk    = (const float*)d_in[5];
    const float* Wv    = (const float*)d_in[6];
    const float* bv    = (const float*)d_in[7];
    const float* Wo    = (const float*)d_in[8];
    const float* bo    = (const float*)d_in[9];
    const float* Wg    = (const float*)d_in[10];
    const float* bg    = (const float*)d_in[11];
    const float* gamma = (const float*)d_in[12];
    const float* beta  = (const float*)d_in[13];
    float* out = (float*)d_out;

    float *q, *k, *v, *g, *attn, *proj, *xr, *cxr, *wqr, *wkr, *wvr, *wgr, *wor;
    cudaGetSymbolAddress((void**)&q,    g_q);
    cudaGetSymbolAddress((void**)&k,    g_k);
    cudaGetSymbolAddress((void**)&v,    g_v);
    cudaGetSymbolAddress((void**)&g,    g_g);
    cudaGetSymbolAddress((void**)&attn, g_attn);
    cudaGetSymbolAddress((void**)&proj, g_proj);
    cudaGetSymbolAddress((void**)&xr,   g_xr);
    cudaGetSymbolAddress((void**)&cxr,  g_cxr);
    cudaGetSymbolAddress((void**)&wqr,  g_wqr);
    cudaGetSymbolAddress((void**)&wkr,  g_wkr);
    cudaGetSymbolAddress((void**)&wvr,  g_wvr);
    cudaGetSymbolAddress((void**)&wgr,  g_wgr);
    cudaGetSymbolAddress((void**)&wor,  g_wor);

    cudaFuncSetAttribute(gemm_mma, cudaFuncAttributeMaxDynamicSharedMemorySize, GEMM_SMEM);
    const int attn_smem = (KRANGE * KPAD + KRANGE * HDIM + 64 * HDIM + 8 * KRANGE) * sizeof(float);
    cudaFuncSetAttribute(attn_win, cudaFuncAttributeMaxDynamicSharedMemorySize, attn_smem);

    // tf32 rounding prep
    const int n4_act = ROWS * DMODEL / 4;
    const int n4_w   = DMODEL * DMODEL / 4;
    tf32_round_kernel<<<(n4_act + 255) / 256, 256>>>((const float4*)X,  (float4*)xr,  n4_act);
    tf32_round_kernel<<<(n4_act + 255) / 256, 256>>>((const float4*)Cx, (float4*)cxr, n4_act);
    tf32_round_kernel<<<(n4_w + 255) / 256, 256>>>((const float4*)Wq, (float4*)wqr, n4_w);
    tf32_round_kernel<<<(n4_w + 255) / 256, 256>>>((const float4*)Wk, (float4*)wkr, n4_w);
    tf32_round_kernel<<<(n4_w + 255) / 256, 256>>>((const float4*)Wv, (float4*)wvr, n4_w);
    tf32_round_kernel<<<(n4_w + 255) / 256, 256>>>((const float4*)Wg, (float4*)wgr, n4_w);
    tf32_round_kernel<<<(n4_w + 255) / 256, 256>>>((const float4*)Wo, (float4*)wor, n4_w);

    dim3 gemm_grid(DMODEL / GBN, ROWS / GBM);    // (8, 64)

    gemm_mma<<<gemm_grid, 256, GEMM_SMEM>>>(xr,  wqr, bq, q);
    gemm_mma<<<gemm_grid, 256, GEMM_SMEM>>>(xr,  wgr, bg, g);
    gemm_mma<<<gemm_grid, 256, GEMM_SMEM>>>(cxr, wkr, bk, k);
    gemm_mma<<<gemm_grid, 256, GEMM_SMEM>>>(cxr, wvr, bv, v);

    dim3 attn_grid(SEQ / 64, NHEAD, BATCH);
    attn_win<<<attn_grid, 256, attn_smem>>>(q, k, v, attn);

    gemm_mma<<<gemm_grid, 256, GEMM_SMEM>>>(attn, wor, bo, proj);

    fused_epilogue<<<ROWS, 256>>>(X, g, proj, gamma, beta, out);
}

// round 5
// speedup vs baseline: 2.9871x; 1.3043x over previous
#include <cuda_runtime.h>
#include <cuda_bf16.h>
#include <math.h>
#include <stdint.h>

// Problem constants
#define BATCH   16
#define SEQ     512
#define DMODEL  1024
#define NHEAD   16
#define HDIM    64
#define ROWS    (BATCH * SEQ)          // 8192
#define WIN     64                     // WINDOW/2
#define SCALE   0.125f                 // 64^-0.5

// ---------------------------------------------------------------------------
// Scratch (device globals: allocation-free per harness rules)
// ---------------------------------------------------------------------------
__device__ float g_q   [ROWS * DMODEL];
__device__ float g_k   [ROWS * DMODEL];
__device__ float g_v   [ROWS * DMODEL];
__device__ float g_g   [ROWS * DMODEL];
__device__ float g_proj[ROWS * DMODEL];
__device__ __nv_bfloat16 g_attnb[ROWS * DMODEL];
// bf16 feeds
__device__ __nv_bfloat16 g_xb  [ROWS * DMODEL];
__device__ __nv_bfloat16 g_cxb [ROWS * DMODEL];
__device__ __nv_bfloat16 g_wqg [2 * DMODEL * DMODEL];   // [Wq; Wg] rows 0..2047
__device__ __nv_bfloat16 g_wkv [2 * DMODEL * DMODEL];   // [Wk; Wv]
__device__ __nv_bfloat16 g_wo  [DMODEL * DMODEL];

// ---------------------------------------------------------------------------
// Helpers
// ---------------------------------------------------------------------------
__device__ __forceinline__ uint32_t smem_u32(const void* p) {
    uint32_t a;
    asm("{ .reg .u64 t; cvta.to.shared.u64 t, %1; cvt.u32.u64 %0, t; }"
        : "=r"(a) : "l"(p));
    return a;
}

// ---------------------------------------------------------------------------
// f32 -> bf16 conversion (4 elems/thread)
// ---------------------------------------------------------------------------
__global__ __launch_bounds__(256) void conv_bf16(
    const float4* __restrict__ in, uint2* __restrict__ out, int n4)
{
    int i = blockIdx.x * 256 + threadIdx.x;
    if (i < n4) {
        float4 v = in[i];
        __nv_bfloat162 lo = __floats2bfloat162_rn(v.x, v.y);
        __nv_bfloat162 hi = __floats2bfloat162_rn(v.z, v.w);
        uint2 o;
        o.x = *(uint32_t*)&lo;
        o.y = *(uint32_t*)&hi;
        out[i] = o;
    }
}

// ---------------------------------------------------------------------------
// bf16 mma GEMM: C[M,Ntot] = A[M,K]*W[Ntot,K]^T + bias, split at nsplit into
// C0/C1 (fused Q+G / K+V). CTA 128x128, BK=64 bf16 (128B rows, chunk-XOR
// swizzle), 256 threads (8 warps 2x4), warp tile 64x32, 4-stage cp.async.
// Fragments via ldmatrix.x4 (conflict-free under the swizzle).
// ---------------------------------------------------------------------------
#define GBM 128
#define GBN 128
#define GBK 64
#define GSTAGES 4
#define GITERS (DMODEL / GBK)                  // 16
#define TILE_BYTES  (GBM * GBK * 2)            // 16384
#define STAGE_BYTES (2 * TILE_BYTES)           // 32768
#define GEMM_SMEM   (GSTAGES * STAGE_BYTES)    // 131072

__device__ __forceinline__ void cp_stage(uint32_t sA, uint32_t sB,
                                         const __nv_bfloat16* __restrict__ Arow,
                                         const __nv_bfloat16* __restrict__ Wrow,
                                         int k0, int t)
{
    #pragma unroll
    for (int i = 0; i < 4; i++) {
        int idx = i * 256 + t;                    // 0..1023
        int row = idx >> 3;                       // 0..127
        int c   = idx & 7;                        // 16B chunk in 128B row
        uint32_t soff = (uint32_t)(row * 128 + ((c ^ (row & 7)) << 4));
        const __nv_bfloat16* ga = Arow + (size_t)row * DMODEL + k0 + c * 8;
        const __nv_bfloat16* gb = Wrow + (size_t)row * DMODEL + k0 + c * 8;
        asm volatile("cp.async.cg.shared.global [%0], [%1], 16;" :: "r"(sA + soff), "l"(ga));
        asm volatile("cp.async.cg.shared.global [%0], [%1], 16;" :: "r"(sB + soff), "l"(gb));
    }
}

#define LDSM_X4(r0, r1, r2, r3, addr) \
    asm volatile("ldmatrix.sync.aligned.m8n8.x4.shared.b16 {%0,%1,%2,%3}, [%4];" \
                 : "=r"(r0), "=r"(r1), "=r"(r2), "=r"(r3) : "r"(addr))

__global__ __launch_bounds__(256, 1)
void gemm_bf16(const __nv_bfloat16* __restrict__ A,   // [8192,1024]
               const __nv_bfloat16* __restrict__ W,   // [Ntot,1024]
               const float* __restrict__ bias0,
               const float* __restrict__ bias1,
               float* __restrict__ C0,                // [8192,1024]
               float* __restrict__ C1,
               int nsplit)
{
    extern __shared__ char smem[];
    const uint32_t sb = smem_u32(smem);
    const int t = threadIdx.x;
    const int bm = blockIdx.y * GBM;
    const int bn = blockIdx.x * GBN;

    const int lane = t & 31;
    const int warp = t >> 5;
    const int grp  = lane >> 2;        // 0..7
    const int tig  = lane & 3;         // 0..3
    const int wm   = warp >> 2;        // 0..1
    const int wn   = warp & 3;         // 0..3
    const int m_base = wm * 64;
    const int n_base = wn * 32;

    // CTA-level output split (Q/G or K/V fusion)
    const bool hiHalf = (bn >= nsplit);
    float* Cx = hiHalf ? C1 : C0;
    const float* biasx = hiHalf ? bias1 : bias0;
    const int bnl = hiHalf ? (bn - nsplit) : bn;

    const __nv_bfloat16* Arow = A + (size_t)bm * DMODEL;
    const __nv_bfloat16* Wrow = W + (size_t)bn * DMODEL;

    // ldmatrix source rows (within stage tile); swizzle selector = lane&7
    const int s7 = lane & 7;
    const int hi16 = lane >> 4;               // chunk parity for A
    const int cb   = (lane >> 3) & 1;         // chunk parity for B
    uint32_t rbA[4], rbB[2];
    #pragma unroll
    for (int fi = 0; fi < 4; fi++)
        rbA[fi] = (uint32_t)((m_base + fi * 16 + (lane & 15)) * 128);
    #pragma unroll
    for (int pr = 0; pr < 2; pr++)
        rbB[pr] = (uint32_t)((n_base + pr * 16 + ((lane >> 4) << 3) + (lane & 7)) * 128);

    float acc[4][4][4];
    #pragma unroll
    for (int fi = 0; fi < 4; fi++)
        #pragma unroll
        for (int fj = 0; fj < 4; fj++)
            #pragma unroll
            for (int r = 0; r < 4; r++)
                acc[fi][fj][r] = 0.0f;

    // Prologue
    #pragma unroll
    for (int s = 0; s < GSTAGES - 1; s++) {
        cp_stage(sb + s * STAGE_BYTES, sb + s * STAGE_BYTES + TILE_BYTES,
                 Arow, Wrow, s * GBK, t);
        asm volatile("cp.async.commit_group;" ::: "memory");
    }

    for (int it = 0; it < GITERS; it++) {
        asm volatile("cp.async.wait_group 2;" ::: "memory");
        __syncthreads();

        const int ps = it + GSTAGES - 1;
        if (ps < GITERS) {
            const int s = ps % GSTAGES;
            cp_stage(sb + s * STAGE_BYTES, sb + s * STAGE_BYTES + TILE_BYTES,
                     Arow, Wrow, ps * GBK, t);
        }
        asm volatile("cp.async.commit_group;" ::: "memory");

        const uint32_t sA = sb + (it % GSTAGES) * STAGE_BYTES;
        const uint32_t sB = sA + TILE_BYTES;

        #pragma unroll
        for (int ks = 0; ks < 4; ks++) {
            const uint32_t coA = (uint32_t)(((2 * ks + hi16) ^ s7) << 4);
            const uint32_t coB = (uint32_t)(((2 * ks + cb)   ^ s7) << 4);

            uint32_t a[4][4];
            #pragma unroll
            for (int fi = 0; fi < 4; fi++)
                LDSM_X4(a[fi][0], a[fi][1], a[fi][2], a[fi][3], sA + rbA[fi] + coA);

            uint32_t b[2][4];
            #pragma unroll
            for (int pr = 0; pr < 2; pr++)
                LDSM_X4(b[pr][0], b[pr][1], b[pr][2], b[pr][3], sB + rbB[pr] + coB);

            #pragma unroll
            for (int fi = 0; fi < 4; fi++)
                #pragma unroll
                for (int fj = 0; fj < 4; fj++) {
                    const int pr = fj >> 1, hf = (fj & 1) << 1;
                    asm volatile(
                        "mma.sync.aligned.m16n8k16.row.col.f32.bf16.bf16.f32 "
                        "{%0,%1,%2,%3}, {%4,%5,%6,%7}, {%8,%9}, {%0,%1,%2,%3};"
                        : "+f"(acc[fi][fj][0]), "+f"(acc[fi][fj][1]),
                          "+f"(acc[fi][fj][2]), "+f"(acc[fi][fj][3])
                        : "r"(a[fi][0]), "r"(a[fi][1]), "r"(a[fi][2]), "r"(a[fi][3]),
                          "r"(b[pr][hf]), "r"(b[pr][hf + 1]));
                }
        }
    }

    // Epilogue: bias + store
    #pragma unroll
    for (int fi = 0; fi < 4; fi++) {
        const int m0 = bm + m_base + fi * 16 + grp;
        #pragma unroll
        for (int fj = 0; fj < 4; fj++) {
            const int n = bnl + n_base + fj * 8 + tig * 2;
            const float2 bv = *(const float2*)&biasx[n];
            float2 v0, v1;
            v0.x = acc[fi][fj][0] + bv.x;
            v0.y = acc[fi][fj][1] + bv.y;
            v1.x = acc[fi][fj][2] + bv.x;
            v1.y = acc[fi][fj][3] + bv.y;
            *(float2*)&Cx[(size_t)m0 * DMODEL + n]       = v0;
            *(float2*)&Cx[(size_t)(m0 + 8) * DMODEL + n] = v1;
        }
    }
}

// ---------------------------------------------------------------------------
// Windowed attention (R1-proven math); output bf16 for the O-proj feed
// ---------------------------------------------------------------------------
#define KRANGE 192
#define KPAD   65

__global__ __launch_bounds__(256) void attn_win(
    const float* __restrict__ Q,
    const float* __restrict__ K,
    const float* __restrict__ V,
    __nv_bfloat16* __restrict__ O)
{
    extern __shared__ float sm[];
    float* Ks = sm;                          // [192][65]
    float* Vs = Ks + KRANGE * KPAD;          // [192][64]
    float* Qs = Vs + KRANGE * HDIM;          // [64][64]
    float* Ps = Qs + 64 * HDIM;              // [8][192]

    const int qt   = blockIdx.x;
    const int h    = blockIdx.y;
    const int b    = blockIdx.z;
    const int t    = threadIdx.x;
    const int lane = t & 31;
    const int w    = t >> 5;

    const int q0    = qt * 64;
    const int kbase = q0 - WIN;

    const float* Qbh = Q + ((size_t)b * SEQ) * DMODEL + h * HDIM;
    const float* Kbh = K + ((size_t)b * SEQ) * DMODEL + h * HDIM;
    const float* Vbh = V + ((size_t)b * SEQ) * DMODEL + h * HDIM;

    for (int idx = t; idx < KRANGE * HDIM; idx += 256) {
        int j = idx >> 6, d = idx & 63;
        int jg = kbase + j;
        float kv = 0.0f, vv = 0.0f;
        if (jg >= 0 && jg < SEQ) {
            kv = Kbh[(size_t)jg * DMODEL + d];
            vv = Vbh[(size_t)jg * DMODEL + d];
        }
        Ks[j * KPAD + d] = kv;
        Vs[j * HDIM + d] = vv;
    }
    for (int idx = t; idx < 64 * HDIM; idx += 256) {
        int q = idx >> 6, d = idx & 63;
        Qs[q * HDIM + d] = Qbh[(size_t)(q0 + q) * DMODEL + d];
    }
    __syncthreads();

    for (int q = w; q < 64; q += 8) {
        const int qi = q0 + q;
        const float* qr = &Qs[q * HDIM];

        float s[6];
        #pragma unroll
        for (int r = 0; r < 6; r++) {
            int j  = r * 32 + lane;
            int jg = kbase + j;
            int dq = qi - jg;
            bool valid = (jg >= 0) && (jg < SEQ) && (dq <= WIN) && (dq >= -WIN);
            float acc = 0.0f;
            const float* kr = &Ks[j * KPAD];
            #pragma unroll
            for (int d = 0; d < HDIM; d++) acc += qr[d] * kr[d];
            s[r] = valid ? acc * SCALE : -1e30f;
        }

        float m = s[0];
        #pragma unroll
        for (int r = 1; r < 6; r++) m = fmaxf(m, s[r]);
        #pragma unroll
        for (int o = 16; o > 0; o >>= 1) m = fmaxf(m, __shfl_xor_sync(0xffffffffu, m, o));
        float sum = 0.0f;
        #pragma unroll
        for (int r = 0; r < 6; r++) { s[r] = __expf(s[r] - m); sum += s[r]; }
        #pragma unroll
        for (int o = 16; o > 0; o >>= 1) sum += __shfl_xor_sync(0xffffffffu, sum, o);
        float inv = 1.0f / sum;
        #pragma unroll
        for (int r = 0; r < 6; r++) Ps[w * KRANGE + r * 32 + lane] = s[r] * inv;
        __syncwarp();

        float o0 = 0.0f, o1 = 0.0f;
        const float* pw = &Ps[w * KRANGE];
        #pragma unroll 4
        for (int j = 0; j < KRANGE; j++) {
            float p = pw[j];
            o0 += p * Vs[j * HDIM + lane];
            o1 += p * Vs[j * HDIM + lane + 32];
        }
        __nv_bfloat16* orow = O + ((size_t)b * SEQ + qi) * DMODEL + h * HDIM;
        orow[lane]      = __float2bfloat16_rn(o0);
        orow[lane + 32] = __float2bfloat16_rn(o1);
        __syncwarp();
    }
}

// ---------------------------------------------------------------------------
// Fused epilogue: gate = sigmoid(gpre); y = 0.5*x + 0.5*gate*proj; LayerNorm
// ---------------------------------------------------------------------------
__global__ __launch_bounds__(256) void fused_epilogue(
    const float* __restrict__ X,
    const float* __restrict__ Gpre,
    const float* __restrict__ Pr,
    const float* __restrict__ gamma,
    const float* __restrict__ beta,
    float* __restrict__ out)
{
    const int r = blockIdx.x;
    const int t = threadIdx.x;
    const float* x = X    + (size_t)r * DMODEL;
    const float* g = Gpre + (size_t)r * DMODEL;
    const float* p = Pr   + (size_t)r * DMODEL;

    float y[4];
    float lsum = 0.0f, lsq = 0.0f;
    #pragma unroll
    for (int i = 0; i < 4; i++) {
        int c = t + i * 256;
        float gate = 1.0f / (1.0f + __expf(-g[c]));
        float v = 0.5f * x[c] + 0.5f * gate * p[c];
        y[i] = v;
        lsum += v;
        lsq  += v * v;
    }

    #pragma unroll
    for (int o = 16; o > 0; o >>= 1) {
        lsum += __shfl_xor_sync(0xffffffffu, lsum, o);
        lsq  += __shfl_xor_sync(0xffffffffu, lsq, o);
    }
    __shared__ float red[2][8];
    const int w = t >> 5, lane = t & 31;
    if (lane == 0) { red[0][w] = lsum; red[1][w] = lsq; }
    __syncthreads();
    float tsum = 0.0f, tsq = 0.0f;
    #pragma unroll
    for (int i = 0; i < 8; i++) { tsum += red[0][i]; tsq += red[1][i]; }

    const float mean = tsum * (1.0f / DMODEL);
    const float var  = tsq * (1.0f / DMODEL) - mean * mean;
    const float rstd = rsqrtf(var + 1e-5f);

    float* o = out + (size_t)r * DMODEL;
    #pragma unroll
    for (int i = 0; i < 4; i++) {
        int c = t + i * 256;
        o[c] = (y[i] - mean) * rstd * gamma[c] + beta[c];
    }
}

// ---------------------------------------------------------------------------
// Launch
// ---------------------------------------------------------------------------
extern "C" void kernel_launch(void* const* d_in, const int* in_sizes, int n_in,
                              void* d_out, int out_size)
{
    const float* X     = (const float*)d_in[0];
    const float* Cx    = (const float*)d_in[1];
    const float* Wq    = (const float*)d_in[2];
    const float* bq    = (const float*)d_in[3];
    const float* Wk    = (const float*)d_in[4];
    const float* bk    = (const float*)d_in[5];
    const float* Wv    = (const float*)d_in[6];
    const float* bv    = (const float*)d_in[7];
    const float* Wo    = (const float*)d_in[8];
    const float* bo    = (const float*)d_in[9];
    const float* Wg    = (const float*)d_in[10];
    const float* bg    = (const float*)d_in[11];
    const float* gamma = (const float*)d_in[12];
    const float* beta  = (const float*)d_in[13];
    float* out = (float*)d_out;

    float *q, *k, *v, *g, *proj;
    __nv_bfloat16 *attnb, *xb, *cxb, *wqg, *wkv, *wo;
    cudaGetSymbolAddress((void**)&q,     g_q);
    cudaGetSymbolAddress((void**)&k,     g_k);
    cudaGetSymbolAddress((void**)&v,     g_v);
    cudaGetSymbolAddress((void**)&g,     g_g);
    cudaGetSymbolAddress((void**)&proj,  g_proj);
    cudaGetSymbolAddress((void**)&attnb, g_attnb);
    cudaGetSymbolAddress((void**)&xb,    g_xb);
    cudaGetSymbolAddress((void**)&cxb,   g_cxb);
    cudaGetSymbolAddress((void**)&wqg,   g_wqg);
    cudaGetSymbolAddress((void**)&wkv,   g_wkv);
    cudaGetSymbolAddress((void**)&wo,    g_wo);

    cudaFuncSetAttribute(gemm_bf16, cudaFuncAttributeMaxDynamicSharedMemorySize, GEMM_SMEM);
    const int attn_smem = (KRANGE * KPAD + KRANGE * HDIM + 64 * HDIM + 8 * KRANGE) * sizeof(float);
    cudaFuncSetAttribute(attn_win, cudaFuncAttributeMaxDynamicSharedMemorySize, attn_smem);

    // bf16 conversion prep
    const int n4_act = ROWS * DMODEL / 4;        // 2M
    const int n4_w   = DMODEL * DMODEL / 4;      // 256K
    conv_bf16<<<(n4_act + 255) / 256, 256>>>((const float4*)X,  (uint2*)xb,  n4_act);
    conv_bf16<<<(n4_act + 255) / 256, 256>>>((const float4*)Cx, (uint2*)cxb, n4_act);
    conv_bf16<<<(n4_w + 255) / 256, 256>>>((const float4*)Wq, (uint2*)wqg, n4_w);
    conv_bf16<<<(n4_w + 255) / 256, 256>>>((const float4*)Wg, (uint2*)(wqg + DMODEL * DMODEL), n4_w);
    conv_bf16<<<(n4_w + 255) / 256, 256>>>((const float4*)Wk, (uint2*)wkv, n4_w);
    conv_bf16<<<(n4_w + 255) / 256, 256>>>((const float4*)Wv, (uint2*)(wkv + DMODEL * DMODEL), n4_w);
    conv_bf16<<<(n4_w + 255) / 256, 256>>>((const float4*)Wo, (uint2*)wo, n4_w);

    // Fused projections: [Q|G] from X, [K|V] from Cx (N=2048 each)
    dim3 qg_grid(2 * DMODEL / GBN, ROWS / GBM);   // (16, 64)
    gemm_bf16<<<qg_grid, 256, GEMM_SMEM>>>(xb,  wqg, bq, bg, q, g, DMODEL);
    gemm_bf16<<<qg_grid, 256, GEMM_SMEM>>>(cxb, wkv, bk, bv, k, v, DMODEL);

    // Windowed attention
    dim3 attn_grid(SEQ / 64, NHEAD, BATCH);
    attn_win<<<attn_grid, 256, attn_smem>>>(q, k, v, attnb);

    // Output projection (N=1024, no split)
    dim3 o_grid(DMODEL / GBN, ROWS / GBM);        // (8, 64)
    gemm_bf16<<<o_grid, 256, GEMM_SMEM>>>(attnb, wo, bo, bo, proj, proj, DMODEL);

    // Gate + blend + LayerNorm
    fused_epilogue<<<ROWS, 256>>>(X, g, proj, gamma, beta, out);
}

// round 6
// speedup vs baseline: 7.9750x; 2.6698x over previous
#include <cuda_runtime.h>
#include <cuda_bf16.h>
#include <math.h>
#include <stdint.h>

// Problem constants
#define BATCH   16
#define SEQ     512
#define DMODEL  1024
#define NHEAD   16
#define HDIM    64
#define ROWS    (BATCH * SEQ)          // 8192
#define WIN     64                     // WINDOW/2
#define SCALE   0.125f                 // 64^-0.5

// ---------------------------------------------------------------------------
// Scratch (device globals: allocation-free per harness rules)
// ---------------------------------------------------------------------------
__device__ float g_g   [ROWS * DMODEL];
__device__ float g_proj[ROWS * DMODEL];
__device__ __nv_bfloat16 g_qb   [ROWS * DMODEL];
__device__ __nv_bfloat16 g_kb   [ROWS * DMODEL];
__device__ __nv_bfloat16 g_vb   [ROWS * DMODEL];
__device__ __nv_bfloat16 g_attnb[ROWS * DMODEL];
// bf16 feeds
__device__ __nv_bfloat16 g_xb  [ROWS * DMODEL];
__device__ __nv_bfloat16 g_cxb [ROWS * DMODEL];
__device__ __nv_bfloat16 g_wqg [2 * DMODEL * DMODEL];   // [Wq; Wg]
__device__ __nv_bfloat16 g_wkv [2 * DMODEL * DMODEL];   // [Wk; Wv]
__device__ __nv_bfloat16 g_wo  [DMODEL * DMODEL];

// ---------------------------------------------------------------------------
// Helpers
// ---------------------------------------------------------------------------
__device__ __forceinline__ uint32_t smem_u32(const void* p) {
    uint32_t a;
    asm("{ .reg .u64 t; cvta.to.shared.u64 t, %1; cvt.u32.u64 %0, t; }"
        : "=r"(a) : "l"(p));
    return a;
}

__device__ __forceinline__ uint32_t pack_bf16(float lo, float hi) {
    __nv_bfloat162 h = __floats2bfloat162_rn(lo, hi);
    return *(uint32_t*)&h;
}

#define LDSM_X4(r0, r1, r2, r3, addr) \
    asm volatile("ldmatrix.sync.aligned.m8n8.x4.shared.b16 {%0,%1,%2,%3}, [%4];" \
                 : "=r"(r0), "=r"(r1), "=r"(r2), "=r"(r3) : "r"(addr))
#define LDSM_X4_T(r0, r1, r2, r3, addr) \
    asm volatile("ldmatrix.sync.aligned.m8n8.x4.trans.shared.b16 {%0,%1,%2,%3}, [%4];" \
                 : "=r"(r0), "=r"(r1), "=r"(r2), "=r"(r3) : "r"(addr))
#define MMA_BF16(c0, c1, c2, c3, a0, a1, a2, a3, b0, b1) \
    asm volatile("mma.sync.aligned.m16n8k16.row.col.f32.bf16.bf16.f32 " \
                 "{%0,%1,%2,%3}, {%4,%5,%6,%7}, {%8,%9}, {%0,%1,%2,%3};" \
                 : "+f"(c0), "+f"(c1), "+f"(c2), "+f"(c3) \
                 : "r"(a0), "r"(a1), "r"(a2), "r"(a3), "r"(b0), "r"(b1))

// ---------------------------------------------------------------------------
// f32 -> bf16 conversion (4 elems/thread)
// ---------------------------------------------------------------------------
__global__ __launch_bounds__(256) void conv_bf16(
    const float4* __restrict__ in, uint2* __restrict__ out, int n4)
{
    int i = blockIdx.x * 256 + threadIdx.x;
    if (i < n4) {
        float4 v = in[i];
        uint2 o;
        o.x = pack_bf16(v.x, v.y);
        o.y = pack_bf16(v.z, v.w);
        out[i] = o;
    }
}

// ---------------------------------------------------------------------------
// bf16 mma GEMM: C[M,Ntot] = A[M,K]*W[Ntot,K]^T + bias, split at nsplit.
// Output per half: bf16 (obf=1) or f32. CTA 128x128, BK=64, 4-stage cp.async.
// ---------------------------------------------------------------------------
#define GBM 128
#define GBN 128
#define GBK 64
#define GSTAGES 4
#define GITERS (DMODEL / GBK)                  // 16
#define TILE_BYTES  (GBM * GBK * 2)            // 16384
#define STAGE_BYTES (2 * TILE_BYTES)           // 32768
#define GEMM_SMEM   (GSTAGES * STAGE_BYTES)    // 131072

__device__ __forceinline__ void cp_stage(uint32_t sA, uint32_t sB,
                                         const __nv_bfloat16* __restrict__ Arow,
                                         const __nv_bfloat16* __restrict__ Wrow,
                                         int k0, int t)
{
    #pragma unroll
    for (int i = 0; i < 4; i++) {
        int idx = i * 256 + t;
        int row = idx >> 3;
        int c   = idx & 7;
        uint32_t soff = (uint32_t)(row * 128 + ((c ^ (row & 7)) << 4));
        const __nv_bfloat16* ga = Arow + (size_t)row * DMODEL + k0 + c * 8;
        const __nv_bfloat16* gb = Wrow + (size_t)row * DMODEL + k0 + c * 8;
        asm volatile("cp.async.cg.shared.global [%0], [%1], 16;" :: "r"(sA + soff), "l"(ga));
        asm volatile("cp.async.cg.shared.global [%0], [%1], 16;" :: "r"(sB + soff), "l"(gb));
    }
}

__global__ __launch_bounds__(256, 1)
void gemm_bf16(const __nv_bfloat16* __restrict__ A,
               const __nv_bfloat16* __restrict__ W,
               const float* __restrict__ bias0,
               const float* __restrict__ bias1,
               void* __restrict__ C0,
               void* __restrict__ C1,
               int nsplit, int obf0, int obf1)
{
    extern __shared__ char smem[];
    const uint32_t sb = smem_u32(smem);
    const int t = threadIdx.x;
    const int bm = blockIdx.y * GBM;
    const int bn = blockIdx.x * GBN;

    const int lane = t & 31;
    const int warp = t >> 5;
    const int grp  = lane >> 2;
    const int tig  = lane & 3;
    const int wm   = warp >> 2;
    const int wn   = warp & 3;
    const int m_base = wm * 64;
    const int n_base = wn * 32;

    const bool hiHalf = (bn >= nsplit);
    void* Cx = hiHalf ? C1 : C0;
    const float* biasx = hiHalf ? bias1 : bias0;
    const int bnl = hiHalf ? (bn - nsplit) : bn;
    const int obf = hiHalf ? obf1 : obf0;

    const __nv_bfloat16* Arow = A + (size_t)bm * DMODEL;
    const __nv_bfloat16* Wrow = W + (size_t)bn * DMODEL;

    const int s7 = lane & 7;
    const int hi16 = lane >> 4;
    const int cb   = (lane >> 3) & 1;
    uint32_t rbA[4], rbB[2];
    #pragma unroll
    for (int fi = 0; fi < 4; fi++)
        rbA[fi] = (uint32_t)((m_base + fi * 16 + (lane & 15)) * 128);
    #pragma unroll
    for (int pr = 0; pr < 2; pr++)
        rbB[pr] = (uint32_t)((n_base + pr * 16 + ((lane >> 4) << 3) + (lane & 7)) * 128);

    float acc[4][4][4];
    #pragma unroll
    for (int fi = 0; fi < 4; fi++)
        #pragma unroll
        for (int fj = 0; fj < 4; fj++)
            #pragma unroll
            for (int r = 0; r < 4; r++)
                acc[fi][fj][r] = 0.0f;

    #pragma unroll
    for (int s = 0; s < GSTAGES - 1; s++) {
        cp_stage(sb + s * STAGE_BYTES, sb + s * STAGE_BYTES + TILE_BYTES,
                 Arow, Wrow, s * GBK, t);
        asm volatile("cp.async.commit_group;" ::: "memory");
    }

    for (int it = 0; it < GITERS; it++) {
        asm volatile("cp.async.wait_group 2;" ::: "memory");
        __syncthreads();

        const int ps = it + GSTAGES - 1;
        if (ps < GITERS) {
            const int s = ps % GSTAGES;
            cp_stage(sb + s * STAGE_BYTES, sb + s * STAGE_BYTES + TILE_BYTES,
                     Arow, Wrow, ps * GBK, t);
        }
        asm volatile("cp.async.commit_group;" ::: "memory");

        const uint32_t sA = sb + (it % GSTAGES) * STAGE_BYTES;
        const uint32_t sB = sA + TILE_BYTES;

        #pragma unroll
        for (int ks = 0; ks < 4; ks++) {
            const uint32_t coA = (uint32_t)(((2 * ks + hi16) ^ s7) << 4);
            const uint32_t coB = (uint32_t)(((2 * ks + cb)   ^ s7) << 4);

            uint32_t a[4][4];
            #pragma unroll
            for (int fi = 0; fi < 4; fi++)
                LDSM_X4(a[fi][0], a[fi][1], a[fi][2], a[fi][3], sA + rbA[fi] + coA);

            uint32_t b[2][4];
            #pragma unroll
            for (int pr = 0; pr < 2; pr++)
                LDSM_X4(b[pr][0], b[pr][1], b[pr][2], b[pr][3], sB + rbB[pr] + coB);

            #pragma unroll
            for (int fi = 0; fi < 4; fi++)
                #pragma unroll
                for (int fj = 0; fj < 4; fj++) {
                    const int pr = fj >> 1, hf = (fj & 1) << 1;
                    MMA_BF16(acc[fi][fj][0], acc[fi][fj][1], acc[fi][fj][2], acc[fi][fj][3],
                             a[fi][0], a[fi][1], a[fi][2], a[fi][3],
                             b[pr][hf], b[pr][hf + 1]);
                }
        }
    }

    #pragma unroll
    for (int fi = 0; fi < 4; fi++) {
        const int m0 = bm + m_base + fi * 16 + grp;
        #pragma unroll
        for (int fj = 0; fj < 4; fj++) {
            const int n = bnl + n_base + fj * 8 + tig * 2;
            const float2 bv = *(const float2*)&biasx[n];
            float v00 = acc[fi][fj][0] + bv.x;
            float v01 = acc[fi][fj][1] + bv.y;
            float v10 = acc[fi][fj][2] + bv.x;
            float v11 = acc[fi][fj][3] + bv.y;
            if (obf) {
                __nv_bfloat16* cp = (__nv_bfloat16*)Cx;
                *(uint32_t*)&cp[(size_t)m0 * DMODEL + n]       = pack_bf16(v00, v01);
                *(uint32_t*)&cp[(size_t)(m0 + 8) * DMODEL + n] = pack_bf16(v10, v11);
            } else {
                float* cp = (float*)Cx;
                *(float2*)&cp[(size_t)m0 * DMODEL + n]       = make_float2(v00, v01);
                *(float2*)&cp[(size_t)(m0 + 8) * DMODEL + n] = make_float2(v10, v11);
            }
        }
    }
}

// ---------------------------------------------------------------------------
// Windowed attention on tensor cores.
// CTA = (b, h, 64-query tile), 128 threads = 4 warps, 16 queries/warp.
// Smem: Q[64][64], K[192][64], V[192][64] bf16, 128B rows, chunk-XOR swizzle.
// QK^T via mma (Q=A, K=B), masked softmax in registers, P repacked as bf16
// A-frags, PV via ldmatrix.trans on V.
// ---------------------------------------------------------------------------
#define KRANGE 192
#define NJT    24            // 192/8 score n-tiles
#define ATTN_SMEM ((64 + KRANGE + KRANGE) * 128)   // 57344 B

__global__ __launch_bounds__(128)
void attn_mma(const __nv_bfloat16* __restrict__ Q,
              const __nv_bfloat16* __restrict__ K,
              const __nv_bfloat16* __restrict__ V,
              __nv_bfloat16* __restrict__ O)
{
    extern __shared__ char smem[];
    const uint32_t sQ = smem_u32(smem);
    const uint32_t sK = sQ + 64 * 128;
    const uint32_t sV = sK + KRANGE * 128;

    const int qt   = blockIdx.x;
    const int h    = blockIdx.y;
    const int b    = blockIdx.z;
    const int t    = threadIdx.x;
    const int lane = t & 31;
    const int w    = t >> 5;
    const int grp  = lane >> 2;
    const int tig  = lane & 3;

    const int q0    = qt * 64;
    const int kbase = q0 - WIN;

    const __nv_bfloat16* Qg = Q + ((size_t)b * SEQ) * DMODEL + h * HDIM;
    const __nv_bfloat16* Kg = K + ((size_t)b * SEQ) * DMODEL + h * HDIM;
    const __nv_bfloat16* Vg = V + ((size_t)b * SEQ) * DMODEL + h * HDIM;

    // ---- Stage Q (64 rows, always valid) ----
    for (int i = t; i < 64 * 8; i += 128) {
        int row = i >> 3, c = i & 7;
        uint32_t dst = sQ + row * 128 + ((c ^ (row & 7)) << 4);
        const __nv_bfloat16* src = Qg + (size_t)(q0 + row) * DMODEL + c * 8;
        asm volatile("cp.async.cg.shared.global [%0], [%1], 16;" :: "r"(dst), "l"(src));
    }
    // ---- Stage K and V (192 rows, zero-fill out of range) ----
    for (int i = t; i < KRANGE * 8; i += 128) {
        int row = i >> 3, c = i & 7;
        int jg = kbase + row;
        uint32_t off = row * 128 + ((c ^ (row & 7)) << 4);
        if ((unsigned)jg < (unsigned)SEQ) {
            const __nv_bfloat16* srck = Kg + (size_t)jg * DMODEL + c * 8;
            const __nv_bfloat16* srcv = Vg + (size_t)jg * DMODEL + c * 8;
            asm volatile("cp.async.cg.shared.global [%0], [%1], 16;" :: "r"(sK + off), "l"(srck));
            asm volatile("cp.async.cg.shared.global [%0], [%1], 16;" :: "r"(sV + off), "l"(srcv));
        } else {
            asm volatile("st.shared.v4.b32 [%0], {%1,%1,%1,%1};" :: "r"(sK + off), "r"(0u));
            asm volatile("st.shared.v4.b32 [%0], {%1,%1,%1,%1};" :: "r"(sV + off), "r"(0u));
        }
    }
    asm volatile("cp.async.commit_group;" ::: "memory");
    asm volatile("cp.async.wait_group 0;" ::: "memory");
    __syncthreads();

    // ---- QK^T: scores[16q x 192j] per warp ----
    const int s7 = lane & 7;
    const int m_base = w * 16;
    // A-frag addresses (Q): rows m_base + (lane&15), chunk parity lane>>4
    const uint32_t rowA = (uint32_t)((m_base + (lane & 15)) * 128);
    const int hi16 = lane >> 4;
    // B-frag addresses (K): rows jt*16 + ((lane>>4)<<3) + (lane&7), chunk parity (lane>>3)&1
    const uint32_t rowBoff = (uint32_t)((((lane >> 4) << 3) + (lane & 7)) * 128);
    const int cb = (lane >> 3) & 1;

    float sc[NJT][4];
    #pragma unroll
    for (int nt = 0; nt < NJT; nt++)
        #pragma unroll
        for (int r = 0; r < 4; r++)
            sc[nt][r] = 0.0f;

    #pragma unroll
    for (int ks = 0; ks < 4; ks++) {
        const uint32_t coA = (uint32_t)(((2 * ks + hi16) ^ s7) << 4);
        const uint32_t coB = (uint32_t)(((2 * ks + cb) ^ s7) << 4);
        uint32_t a0, a1, a2, a3;
        LDSM_X4(a0, a1, a2, a3, sQ + rowA + coA);
        #pragma unroll
        for (int jt = 0; jt < 12; jt++) {
            uint32_t b0, b1, b2, b3;
            LDSM_X4(b0, b1, b2, b3, sK + (uint32_t)(jt * 16 * 128) + rowBoff + coB);
            MMA_BF16(sc[2 * jt][0], sc[2 * jt][1], sc[2 * jt][2], sc[2 * jt][3],
                     a0, a1, a2, a3, b0, b1);
            MMA_BF16(sc[2 * jt + 1][0], sc[2 * jt + 1][1], sc[2 * jt + 1][2], sc[2 * jt + 1][3],
                     a0, a1, a2, a3, b2, b3);
        }
    }

    // ---- Mask + scale; softmax (rows grp and grp+8) ----
    const int qi0 = q0 + m_base + grp;
    const int qi1 = qi0 + 8;
    #pragma unroll
    for (int nt = 0; nt < NJT; nt++) {
        const int jg0 = kbase + nt * 8 + tig * 2;
        const int jg1 = jg0 + 1;
        bool v00 = ((unsigned)jg0 < (unsigned)SEQ) && ((unsigned)(qi0 - jg0 + WIN) <= 2u * WIN);
        bool v01 = ((unsigned)jg1 < (unsigned)SEQ) && ((unsigned)(qi0 - jg1 + WIN) <= 2u * WIN);
        bool v10 = ((unsigned)jg0 < (unsigned)SEQ) && ((unsigned)(qi1 - jg0 + WIN) <= 2u * WIN);
        bool v11 = ((unsigned)jg1 < (unsigned)SEQ) && ((unsigned)(qi1 - jg1 + WIN) <= 2u * WIN);
        sc[nt][0] = v00 ? sc[nt][0] * SCALE : -1e30f;
        sc[nt][1] = v01 ? sc[nt][1] * SCALE : -1e30f;
        sc[nt][2] = v10 ? sc[nt][2] * SCALE : -1e30f;
        sc[nt][3] = v11 ? sc[nt][3] * SCALE : -1e30f;
    }

    float m0 = -1e30f, m1 = -1e30f;
    #pragma unroll
    for (int nt = 0; nt < NJT; nt++) {
        m0 = fmaxf(m0, fmaxf(sc[nt][0], sc[nt][1]));
        m1 = fmaxf(m1, fmaxf(sc[nt][2], sc[nt][3]));
    }
    #pragma unroll
    for (int o = 1; o <= 2; o <<= 1) {
        m0 = fmaxf(m0, __shfl_xor_sync(0xffffffffu, m0, o));
        m1 = fmaxf(m1, __shfl_xor_sync(0xffffffffu, m1, o));
    }
    float s0 = 0.0f, s1 = 0.0f;
    #pragma unroll
    for (int nt = 0; nt < NJT; nt++) {
        sc[nt][0] = __expf(sc[nt][0] - m0);
        sc[nt][1] = __expf(sc[nt][1] - m0);
        sc[nt][2] = __expf(sc[nt][2] - m1);
        sc[nt][3] = __expf(sc[nt][3] - m1);
        s0 += sc[nt][0] + sc[nt][1];
        s1 += sc[nt][2] + sc[nt][3];
    }
    #pragma unroll
    for (int o = 1; o <= 2; o <<= 1) {
        s0 += __shfl_xor_sync(0xffffffffu, s0, o);
        s1 += __shfl_xor_sync(0xffffffffu, s1, o);
    }
    const float inv0 = 1.0f / s0;
    const float inv1 = 1.0f / s1;

    // ---- PV: out[16q x 64d], k = 192 j ----
    float ov[8][4];
    #pragma unroll
    for (int nt = 0; nt < 8; nt++)
        #pragma unroll
        for (int r = 0; r < 4; r++)
            ov[nt][r] = 0.0f;

    // V trans-frag addresses: rows kj*16 + (lane&15), chunk dt*2 + (lane>>4)
    const uint32_t rowV = (uint32_t)((lane & 15) * 128);
    #pragma unroll
    for (int kj = 0; kj < 12; kj++) {
        uint32_t ra0 = pack_bf16(sc[2 * kj][0] * inv0,     sc[2 * kj][1] * inv0);
        uint32_t ra1 = pack_bf16(sc[2 * kj][2] * inv1,     sc[2 * kj][3] * inv1);
        uint32_t ra2 = pack_bf16(sc[2 * kj + 1][0] * inv0, sc[2 * kj + 1][1] * inv0);
        uint32_t ra3 = pack_bf16(sc[2 * kj + 1][2] * inv1, sc[2 * kj + 1][3] * inv1);
        const uint32_t vbase = sV + (uint32_t)(kj * 16 * 128) + rowV;
        #pragma unroll
        for (int dt = 0; dt < 4; dt++) {
            const int row = kj * 16 + (lane & 15);
            const uint32_t cd = (uint32_t)(dt * 2 + (lane >> 4));
            uint32_t b0, b1, b2, b3;
            LDSM_X4_T(b0, b1, b2, b3, vbase + ((cd ^ (uint32_t)(row & 7)) << 4));
            MMA_BF16(ov[2 * dt][0], ov[2 * dt][1], ov[2 * dt][2], ov[2 * dt][3],
                     ra0, ra1, ra2, ra3, b0, b1);
            MMA_BF16(ov[2 * dt + 1][0], ov[2 * dt + 1][1], ov[2 * dt + 1][2], ov[2 * dt + 1][3],
                     ra0, ra1, ra2, ra3, b2, b3);
        }
    }

    // ---- Store bf16 output ----
    __nv_bfloat16* O0 = O + ((size_t)b * SEQ + qi0) * DMODEL + h * HDIM;
    __nv_bfloat16* O1 = O + ((size_t)b * SEQ + qi1) * DMODEL + h * HDIM;
    #pragma unroll
    for (int nt = 0; nt < 8; nt++) {
        const int d = nt * 8 + tig * 2;
        *(uint32_t*)&O0[d] = pack_bf16(ov[nt][0], ov[nt][1]);
        *(uint32_t*)&O1[d] = pack_bf16(ov[nt][2], ov[nt][3]);
    }
}

// ---------------------------------------------------------------------------
// Fused epilogue: gate = sigmoid(gpre); y = 0.5*x + 0.5*gate*proj; LayerNorm
// ---------------------------------------------------------------------------
__global__ __launch_bounds__(256) void fused_epilogue(
    const float* __restrict__ X,
    const float* __restrict__ Gpre,
    const float* __restrict__ Pr,
    const float* __restrict__ gamma,
    const float* __restrict__ beta,
    float* __restrict__ out)
{
    const int r = blockIdx.x;
    const int t = threadIdx.x;
    const float* x = X    + (size_t)r * DMODEL;
    const float* g = Gpre + (size_t)r * DMODEL;
    const float* p = Pr   + (size_t)r * DMODEL;

    float y[4];
    float lsum = 0.0f, lsq = 0.0f;
    #pragma unroll
    for (int i = 0; i < 4; i++) {
        int c = t + i * 256;
        float gate = 1.0f / (1.0f + __expf(-g[c]));
        float v = 0.5f * x[c] + 0.5f * gate * p[c];
        y[i] = v;
        lsum += v;
        lsq  += v * v;
    }

    #pragma unroll
    for (int o = 16; o > 0; o >>= 1) {
        lsum += __shfl_xor_sync(0xffffffffu, lsum, o);
        lsq  += __shfl_xor_sync(0xffffffffu, lsq, o);
    }
    __shared__ float red[2][8];
    const int w = t >> 5, lane = t & 31;
    if (lane == 0) { red[0][w] = lsum; red[1][w] = lsq; }
    __syncthreads();
    float tsum = 0.0f, tsq = 0.0f;
    #pragma unroll
    for (int i = 0; i < 8; i++) { tsum += red[0][i]; tsq += red[1][i]; }

    const float mean = tsum * (1.0f / DMODEL);
    const float var  = tsq * (1.0f / DMODEL) - mean * mean;
    const float rstd = rsqrtf(var + 1e-5f);

    float* o = out + (size_t)r * DMODEL;
    #pragma unroll
    for (int i = 0; i < 4; i++) {
        int c = t + i * 256;
        o[c] = (y[i] - mean) * rstd * gamma[c] + beta[c];
    }
}

// ---------------------------------------------------------------------------
// Launch
// ---------------------------------------------------------------------------
extern "C" void kernel_launch(void* const* d_in, const int* in_sizes, int n_in,
                              void* d_out, int out_size)
{
    const float* X     = (const float*)d_in[0];
    const float* Cx    = (const float*)d_in[1];
    const float* Wq    = (const float*)d_in[2];
    const float* bq    = (const float*)d_in[3];
    const float* Wk    = (const float*)d_in[4];
    const float* bk    = (const float*)d_in[5];
    const float* Wv    = (const float*)d_in[6];
    const float* bv    = (const float*)d_in[7];
    const float* Wo    = (const float*)d_in[8];
    const float* bo    = (const float*)d_in[9];
    const float* Wg    = (const float*)d_in[10];
    const float* bg    = (const float*)d_in[11];
    const float* gamma = (const float*)d_in[12];
    const float* beta  = (const float*)d_in[13];
    float* out = (float*)d_out;

    float *g, *proj;
    __nv_bfloat16 *qb, *kb, *vb, *attnb, *xb, *cxb, *wqg, *wkv, *wo;
    cudaGetSymbolAddress((void**)&g,     g_g);
    cudaGetSymbolAddress((void**)&proj,  g_proj);
    cudaGetSymbolAddress((void**)&qb,    g_qb);
    cudaGetSymbolAddress((void**)&kb,    g_kb);
    cudaGetSymbolAddress((void**)&vb,    g_vb);
    cudaGetSymbolAddress((void**)&attnb, g_attnb);
    cudaGetSymbolAddress((void**)&xb,    g_xb);
    cudaGetSymbolAddress((void**)&cxb,   g_cxb);
    cudaGetSymbolAddress((void**)&wqg,   g_wqg);
    cudaGetSymbolAddress((void**)&wkv,   g_wkv);
    cudaGetSymbolAddress((void**)&wo,    g_wo);

    cudaFuncSetAttribute(gemm_bf16, cudaFuncAttributeMaxDynamicSharedMemorySize, GEMM_SMEM);
    cudaFuncSetAttribute(attn_mma, cudaFuncAttributeMaxDynamicSharedMemorySize, ATTN_SMEM);

    // bf16 conversion prep
    const int n4_act = ROWS * DMODEL / 4;
    const int n4_w   = DMODEL * DMODEL / 4;
    conv_bf16<<<(n4_act + 255) / 256, 256>>>((const float4*)X,  (uint2*)xb,  n4_act);
    conv_bf16<<<(n4_act + 255) / 256, 256>>>((const float4*)Cx, (uint2*)cxb, n4_act);
    conv_bf16<<<(n4_w + 255) / 256, 256>>>((const float4*)Wq, (uint2*)wqg, n4_w);
    conv_bf16<<<(n4_w + 255) / 256, 256>>>((const float4*)Wg, (uint2*)(wqg + DMODEL * DMODEL), n4_w);
    conv_bf16<<<(n4_w + 255) / 256, 256>>>((const float4*)Wk, (uint2*)wkv, n4_w);
    conv_bf16<<<(n4_w + 255) / 256, 256>>>((const float4*)Wv, (uint2*)(wkv + DMODEL * DMODEL), n4_w);
    conv_bf16<<<(n4_w + 255) / 256, 256>>>((const float4*)Wo, (uint2*)wo, n4_w);

    // Fused projections: [Q|G] from X (q->bf16, g->f32); [K|V] from Cx (both bf16)
    dim3 qg_grid(2 * DMODEL / GBN, ROWS / GBM);   // (16, 64)
    gemm_bf16<<<qg_grid, 256, GEMM_SMEM>>>(xb,  wqg, bq, bg, qb, g,  DMODEL, 1, 0);
    gemm_bf16<<<qg_grid, 256, GEMM_SMEM>>>(cxb, wkv, bk, bv, kb, vb, DMODEL, 1, 1);

    // Tensor-core windowed attention
    dim3 attn_grid(SEQ / 64, NHEAD, BATCH);       // (8, 16, 16)
    attn_mma<<<attn_grid, 128, ATTN_SMEM>>>(qb, kb, vb, attnb);

    // Output projection (f32 out)
    dim3 o_grid(DMODEL / GBN, ROWS / GBM);        // (8, 64)
    gemm_bf16<<<o_grid, 256, GEMM_SMEM>>>(attnb, wo, bo, bo, proj, proj, DMODEL, 0, 0);

    // Gate + blend + LayerNorm
    fused_epilogue<<<ROWS, 256>>>(X, g, proj, gamma, beta, out);
}

// round 7
// speedup vs baseline: 8.0151x; 1.0050x over previous
#include <cuda_runtime.h>
#include <cuda_bf16.h>
#include <math.h>
#include <stdint.h>

// Problem constants
#define BATCH   16
#define SEQ     512
#define DMODEL  1024
#define NHEAD   16
#define HDIM    64
#define ROWS    (BATCH * SEQ)          // 8192
#define WIN     64                     // WINDOW/2
#define SCALE   0.125f                 // 64^-0.5

// ---------------------------------------------------------------------------
// Scratch (device globals: allocation-free per harness rules)
// ---------------------------------------------------------------------------
__device__ float g_g  [ROWS * DMODEL];
__device__ float g_y  [ROWS * DMODEL];          // gated blend result (pre-LN)
__device__ __nv_bfloat16 g_qb   [ROWS * DMODEL];
__device__ __nv_bfloat16 g_kb   [ROWS * DMODEL];
__device__ __nv_bfloat16 g_vb   [ROWS * DMODEL];
__device__ __nv_bfloat16 g_attnb[ROWS * DMODEL];
__device__ __nv_bfloat16 g_xb  [ROWS * DMODEL];
__device__ __nv_bfloat16 g_cxb [ROWS * DMODEL];
__device__ __nv_bfloat16 g_wqg [2 * DMODEL * DMODEL];   // [Wq; Wg]
__device__ __nv_bfloat16 g_wkv [2 * DMODEL * DMODEL];   // [Wk; Wv]
__device__ __nv_bfloat16 g_wo  [DMODEL * DMODEL];

// ---------------------------------------------------------------------------
// Helpers
// ---------------------------------------------------------------------------
__device__ __forceinline__ uint32_t smem_u32(const void* p) {
    uint32_t a;
    asm("{ .reg .u64 t; cvta.to.shared.u64 t, %1; cvt.u32.u64 %0, t; }"
        : "=r"(a) : "l"(p));
    return a;
}

__device__ __forceinline__ uint32_t pack_bf16(float lo, float hi) {
    __nv_bfloat162 h = __floats2bfloat162_rn(lo, hi);
    return *(uint32_t*)&h;
}

#define LDSM_X4(r0, r1, r2, r3, addr) \
    asm volatile("ldmatrix.sync.aligned.m8n8.x4.shared.b16 {%0,%1,%2,%3}, [%4];" \
                 : "=r"(r0), "=r"(r1), "=r"(r2), "=r"(r3) : "r"(addr))
#define LDSM_X4_T(r0, r1, r2, r3, addr) \
    asm volatile("ldmatrix.sync.aligned.m8n8.x4.trans.shared.b16 {%0,%1,%2,%3}, [%4];" \
                 : "=r"(r0), "=r"(r1), "=r"(r2), "=r"(r3) : "r"(addr))
#define MMA_BF16(c0, c1, c2, c3, a0, a1, a2, a3, b0, b1) \
    asm volatile("mma.sync.aligned.m16n8k16.row.col.f32.bf16.bf16.f32 " \
                 "{%0,%1,%2,%3}, {%4,%5,%6,%7}, {%8,%9}, {%0,%1,%2,%3};" \
                 : "+f"(c0), "+f"(c1), "+f"(c2), "+f"(c3) \
                 : "r"(a0), "r"(a1), "r"(a2), "r"(a3), "r"(b0), "r"(b1))

// ---------------------------------------------------------------------------
// Fused f32->bf16 conversions
// ---------------------------------------------------------------------------
__global__ __launch_bounds__(256) void conv_acts(
    const float4* __restrict__ X, const float4* __restrict__ Cx,
    uint2* __restrict__ xb, uint2* __restrict__ cxb)
{
    int i = blockIdx.x * 256 + threadIdx.x;          // 0 .. 2M-1
    const float4* src = blockIdx.y ? Cx : X;
    uint2* dst = blockIdx.y ? cxb : xb;
    float4 v = src[i];
    uint2 o;
    o.x = pack_bf16(v.x, v.y);
    o.y = pack_bf16(v.z, v.w);
    dst[i] = o;
}

__global__ __launch_bounds__(256) void conv_weights(
    const float4* __restrict__ Wq, const float4* __restrict__ Wg,
    const float4* __restrict__ Wk, const float4* __restrict__ Wv,
    const float4* __restrict__ Wo,
    uint2* __restrict__ wqg, uint2* __restrict__ wkv, uint2* __restrict__ wo)
{
    int i = blockIdx.x * 256 + threadIdx.x;          // 0 .. 256K-1
    int s = blockIdx.y;                              // 0..4
    const float4* src = (s == 0) ? Wq : (s == 1) ? Wg : (s == 2) ? Wk
                       : (s == 3) ? Wv : Wo;
    uint2* dst = (s == 0) ? wqg
               : (s == 1) ? (wqg + DMODEL * DMODEL / 4)
               : (s == 2) ? wkv
               : (s == 3) ? (wkv + DMODEL * DMODEL / 4)
               : wo;
    float4 v = src[i];
    uint2 o;
    o.x = pack_bf16(v.x, v.y);
    o.y = pack_bf16(v.z, v.w);
    dst[i] = o;
}

// ---------------------------------------------------------------------------
// bf16 mma GEMM v2: C[M,Ntot] = A[M,K]*W[Ntot,K]^T + bias, split at nsplit.
// CTA 256x128, 256 threads (8 warps 4x2), warp tile 64x64, BK=64, 4 stages.
// Optional fused gated-blend epilogue (epiX/epiG non-null):
//   y = 0.5*X + 0.5*sigmoid(G)*(acc+bias)
// ---------------------------------------------------------------------------
#define GBM 256
#define GBN 128
#define GBK 64
#define GSTAGES 4
#define GITERS (DMODEL / GBK)                  // 16
#define TILE_A_BYTES (GBM * GBK * 2)           // 32768
#define TILE_B_BYTES (GBN * GBK * 2)           // 16384
#define STAGE_BYTES (TILE_A_BYTES + TILE_B_BYTES)  // 49152
#define GEMM_SMEM   (GSTAGES * STAGE_BYTES)        // 196608

__device__ __forceinline__ void cp_stage(uint32_t sA, uint32_t sB,
                                         const __nv_bfloat16* __restrict__ Arow,
                                         const __nv_bfloat16* __restrict__ Wrow,
                                         int k0, int t)
{
    #pragma unroll
    for (int i = 0; i < 12; i++) {
        int idx = i * 256 + t;                    // 0..3071
        int row = idx >> 3;                       // 0..383 (A:0-255, B:256-383)
        int c   = idx & 7;
        uint32_t soff = ((uint32_t)c ^ (uint32_t)(row & 7)) << 4;
        if (row < GBM) {
            const __nv_bfloat16* ga = Arow + (size_t)row * DMODEL + k0 + c * 8;
            asm volatile("cp.async.cg.shared.global [%0], [%1], 16;"
                         :: "r"(sA + (uint32_t)row * 128 + soff), "l"(ga));
        } else {
            int rb = row - GBM;
            const __nv_bfloat16* gb = Wrow + (size_t)rb * DMODEL + k0 + c * 8;
            asm volatile("cp.async.cg.shared.global [%0], [%1], 16;"
                         :: "r"(sB + (uint32_t)rb * 128 + soff), "l"(gb));
        }
    }
}

__global__ __launch_bounds__(256, 1)
void gemm_bf16(const __nv_bfloat16* __restrict__ A,
               const __nv_bfloat16* __restrict__ W,
               const float* __restrict__ bias0,
               const float* __restrict__ bias1,
               void* __restrict__ C0,
               void* __restrict__ C1,
               int nsplit, int obf0, int obf1,
               const float* __restrict__ epiX,
               const float* __restrict__ epiG)
{
    extern __shared__ char smem[];
    const uint32_t sb = smem_u32(smem);
    const int t = threadIdx.x;
    const int bm = blockIdx.y * GBM;
    const int bn = blockIdx.x * GBN;

    const int lane = t & 31;
    const int warp = t >> 5;
    const int grp  = lane >> 2;
    const int tig  = lane & 3;
    const int wm   = warp >> 1;        // 0..3
    const int wn   = warp & 1;         // 0..1
    const int m_base = wm * 64;
    const int n_base = wn * 64;

    const bool hiHalf = (bn >= nsplit);
    void* Cx = hiHalf ? C1 : C0;
    const float* biasx = hiHalf ? bias1 : bias0;
    const int bnl = hiHalf ? (bn - nsplit) : bn;
    const int obf = hiHalf ? obf1 : obf0;

    const __nv_bfloat16* Arow = A + (size_t)bm * DMODEL;
    const __nv_bfloat16* Wrow = W + (size_t)bn * DMODEL;

    const int s7 = lane & 7;
    const int hi16 = lane >> 4;
    const int cb   = (lane >> 3) & 1;
    uint32_t rbA[4], rbB[4];
    #pragma unroll
    for (int fi = 0; fi < 4; fi++)
        rbA[fi] = (uint32_t)((m_base + fi * 16 + (lane & 15)) * 128);
    #pragma unroll
    for (int pr = 0; pr < 4; pr++)
        rbB[pr] = (uint32_t)((n_base + pr * 16 + ((lane >> 4) << 3) + (lane & 7)) * 128);

    float acc[4][8][4];
    #pragma unroll
    for (int fi = 0; fi < 4; fi++)
        #pragma unroll
        for (int fj = 0; fj < 8; fj++)
            #pragma unroll
            for (int r = 0; r < 4; r++)
                acc[fi][fj][r] = 0.0f;

    #pragma unroll
    for (int s = 0; s < GSTAGES - 1; s++) {
        cp_stage(sb + s * STAGE_BYTES, sb + s * STAGE_BYTES + TILE_A_BYTES,
                 Arow, Wrow, s * GBK, t);
        asm volatile("cp.async.commit_group;" ::: "memory");
    }

    for (int it = 0; it < GITERS; it++) {
        asm volatile("cp.async.wait_group 2;" ::: "memory");
        __syncthreads();

        const int ps = it + GSTAGES - 1;
        if (ps < GITERS) {
            const int s = ps % GSTAGES;
            cp_stage(sb + s * STAGE_BYTES, sb + s * STAGE_BYTES + TILE_A_BYTES,
                     Arow, Wrow, ps * GBK, t);
        }
        asm volatile("cp.async.commit_group;" ::: "memory");

        const uint32_t sA = sb + (it % GSTAGES) * STAGE_BYTES;
        const uint32_t sB = sA + TILE_A_BYTES;

        #pragma unroll
        for (int ks = 0; ks < 4; ks++) {
            const uint32_t coA = (uint32_t)(((2 * ks + hi16) ^ s7) << 4);
            const uint32_t coB = (uint32_t)(((2 * ks + cb)   ^ s7) << 4);

            uint32_t a[4][4];
            #pragma unroll
            for (int fi = 0; fi < 4; fi++)
                LDSM_X4(a[fi][0], a[fi][1], a[fi][2], a[fi][3], sA + rbA[fi] + coA);

            uint32_t b[4][4];
            #pragma unroll
            for (int pr = 0; pr < 4; pr++)
                LDSM_X4(b[pr][0], b[pr][1], b[pr][2], b[pr][3], sB + rbB[pr] + coB);

            #pragma unroll
            for (int fi = 0; fi < 4; fi++)
                #pragma unroll
                for (int fj = 0; fj < 8; fj++) {
                    const int pr = fj >> 1, hf = (fj & 1) << 1;
                    MMA_BF16(acc[fi][fj][0], acc[fi][fj][1], acc[fi][fj][2], acc[fi][fj][3],
                             a[fi][0], a[fi][1], a[fi][2], a[fi][3],
                             b[pr][hf], b[pr][hf + 1]);
                }
        }
    }

    // Epilogue
    #pragma unroll
    for (int fi = 0; fi < 4; fi++) {
        const int m0 = bm + m_base + fi * 16 + grp;
        #pragma unroll
        for (int fj = 0; fj < 8; fj++) {
            const int n = bnl + n_base + fj * 8 + tig * 2;
            const float2 bv = *(const float2*)&biasx[n];
            float v00 = acc[fi][fj][0] + bv.x;
            float v01 = acc[fi][fj][1] + bv.y;
            float v10 = acc[fi][fj][2] + bv.x;
            float v11 = acc[fi][fj][3] + bv.y;
            const size_t i0 = (size_t)m0 * DMODEL + n;
            const size_t i1 = (size_t)(m0 + 8) * DMODEL + n;
            if (epiX) {
                // gated blend: y = 0.5*X + 0.5*sigmoid(G)*proj
                float2 x0 = *(const float2*)&epiX[i0];
                float2 x1 = *(const float2*)&epiX[i1];
                float2 g0 = *(const float2*)&epiG[i0];
                float2 g1 = *(const float2*)&epiG[i1];
                v00 = 0.5f * x0.x + 0.5f * v00 / (1.0f + __expf(-g0.x));
                v01 = 0.5f * x0.y + 0.5f * v01 / (1.0f + __expf(-g0.y));
                v10 = 0.5f * x1.x + 0.5f * v10 / (1.0f + __expf(-g1.x));
                v11 = 0.5f * x1.y + 0.5f * v11 / (1.0f + __expf(-g1.y));
            }
            if (obf) {
                __nv_bfloat16* cp = (__nv_bfloat16*)Cx;
                *(uint32_t*)&cp[i0] = pack_bf16(v00, v01);
                *(uint32_t*)&cp[i1] = pack_bf16(v10, v11);
            } else {
                float* cp = (float*)Cx;
                *(float2*)&cp[i0] = make_float2(v00, v01);
                *(float2*)&cp[i1] = make_float2(v10, v11);
            }
        }
    }
}

// ---------------------------------------------------------------------------
// Windowed attention on tensor cores (R6-proven).
// ---------------------------------------------------------------------------
#define KRANGE 192
#define NJT    24
#define ATTN_SMEM ((64 + KRANGE + KRANGE) * 128)   // 57344 B

__global__ __launch_bounds__(128)
void attn_mma(const __nv_bfloat16* __restrict__ Q,
              const __nv_bfloat16* __restrict__ K,
              const __nv_bfloat16* __restrict__ V,
              __nv_bfloat16* __restrict__ O)
{
    extern __shared__ char smem[];
    const uint32_t sQ = smem_u32(smem);
    const uint32_t sK = sQ + 64 * 128;
    const uint32_t sV = sK + KRANGE * 128;

    const int qt   = blockIdx.x;
    const int h    = blockIdx.y;
    const int b    = blockIdx.z;
    const int t    = threadIdx.x;
    const int lane = t & 31;
    const int w    = t >> 5;
    const int grp  = lane >> 2;
    const int tig  = lane & 3;

    const int q0    = qt * 64;
    const int kbase = q0 - WIN;

    const __nv_bfloat16* Qg = Q + ((size_t)b * SEQ) * DMODEL + h * HDIM;
    const __nv_bfloat16* Kg = K + ((size_t)b * SEQ) * DMODEL + h * HDIM;
    const __nv_bfloat16* Vg = V + ((size_t)b * SEQ) * DMODEL + h * HDIM;

    for (int i = t; i < 64 * 8; i += 128) {
        int row = i >> 3, c = i & 7;
        uint32_t dst = sQ + row * 128 + ((c ^ (row & 7)) << 4);
        const __nv_bfloat16* src = Qg + (size_t)(q0 + row) * DMODEL + c * 8;
        asm volatile("cp.async.cg.shared.global [%0], [%1], 16;" :: "r"(dst), "l"(src));
    }
    for (int i = t; i < KRANGE * 8; i += 128) {
        int row = i >> 3, c = i & 7;
        int jg = kbase + row;
        uint32_t off = row * 128 + ((c ^ (row & 7)) << 4);
        if ((unsigned)jg < (unsigned)SEQ) {
            const __nv_bfloat16* srck = Kg + (size_t)jg * DMODEL + c * 8;
            const __nv_bfloat16* srcv = Vg + (size_t)jg * DMODEL + c * 8;
            asm volatile("cp.async.cg.shared.global [%0], [%1], 16;" :: "r"(sK + off), "l"(srck));
            asm volatile("cp.async.cg.shared.global [%0], [%1], 16;" :: "r"(sV + off), "l"(srcv));
        } else {
            asm volatile("st.shared.v4.b32 [%0], {%1,%1,%1,%1};" :: "r"(sK + off), "r"(0u));
            asm volatile("st.shared.v4.b32 [%0], {%1,%1,%1,%1};" :: "r"(sV + off), "r"(0u));
        }
    }
    asm volatile("cp.async.commit_group;" ::: "memory");
    asm volatile("cp.async.wait_group 0;" ::: "memory");
    __syncthreads();

    const int s7 = lane & 7;
    const int m_base = w * 16;
    const uint32_t rowA = (uint32_t)((m_base + (lane & 15)) * 128);
    const int hi16 = lane >> 4;
    const uint32_t rowBoff = (uint32_t)((((lane >> 4) << 3) + (lane & 7)) * 128);
    const int cb = (lane >> 3) & 1;

    float sc[NJT][4];
    #pragma unroll
    for (int nt = 0; nt < NJT; nt++)
        #pragma unroll
        for (int r = 0; r < 4; r++)
            sc[nt][r] = 0.0f;

    #pragma unroll
    for (int ks = 0; ks < 4; ks++) {
        const uint32_t coA = (uint32_t)(((2 * ks + hi16) ^ s7) << 4);
        const uint32_t coB = (uint32_t)(((2 * ks + cb) ^ s7) << 4);
        uint32_t a0, a1, a2, a3;
        LDSM_X4(a0, a1, a2, a3, sQ + rowA + coA);
        #pragma unroll
        for (int jt = 0; jt < 12; jt++) {
            uint32_t b0, b1, b2, b3;
            LDSM_X4(b0, b1, b2, b3, sK + (uint32_t)(jt * 16 * 128) + rowBoff + coB);
            MMA_BF16(sc[2 * jt][0], sc[2 * jt][1], sc[2 * jt][2], sc[2 * jt][3],
                     a0, a1, a2, a3, b0, b1);
            MMA_BF16(sc[2 * jt + 1][0], sc[2 * jt + 1][1], sc[2 * jt + 1][2], sc[2 * jt + 1][3],
                     a0, a1, a2, a3, b2, b3);
        }
    }

    const int qi0 = q0 + m_base + grp;
    const int qi1 = qi0 + 8;
    #pragma unroll
    for (int nt = 0; nt < NJT; nt++) {
        const int jg0 = kbase + nt * 8 + tig * 2;
        const int jg1 = jg0 + 1;
        bool v00 = ((unsigned)jg0 < (unsigned)SEQ) && ((unsigned)(qi0 - jg0 + WIN) <= 2u * WIN);
        bool v01 = ((unsigned)jg1 < (unsigned)SEQ) && ((unsigned)(qi0 - jg1 + WIN) <= 2u * WIN);
        bool v10 = ((unsigned)jg0 < (unsigned)SEQ) && ((unsigned)(qi1 - jg0 + WIN) <= 2u * WIN);
        bool v11 = ((unsigned)jg1 < (unsigned)SEQ) && ((unsigned)(qi1 - jg1 + WIN) <= 2u * WIN);
        sc[nt][0] = v00 ? sc[nt][0] * SCALE : -1e30f;
        sc[nt][1] = v01 ? sc[nt][1] * SCALE : -1e30f;
        sc[nt][2] = v10 ? sc[nt][2] * SCALE : -1e30f;
        sc[nt][3] = v11 ? sc[nt][3] * SCALE : -1e30f;
    }

    float m0 = -1e30f, m1 = -1e30f;
    #pragma unroll
    for (int nt = 0; nt < NJT; nt++) {
        m0 = fmaxf(m0, fmaxf(sc[nt][0], sc[nt][1]));
        m1 = fmaxf(m1, fmaxf(sc[nt][2], sc[nt][3]));
    }
    #pragma unroll
    for (int o = 1; o <= 2; o <<= 1) {
        m0 = fmaxf(m0, __shfl_xor_sync(0xffffffffu, m0, o));
        m1 = fmaxf(m1, __shfl_xor_sync(0xffffffffu, m1, o));
    }
    float s0 = 0.0f, s1 = 0.0f;
    #pragma unroll
    for (int nt = 0; nt < NJT; nt++) {
        sc[nt][0] = __expf(sc[nt][0] - m0);
        sc[nt][1] = __expf(sc[nt][1] - m0);
        sc[nt][2] = __expf(sc[nt][2] - m1);
        sc[nt][3] = __expf(sc[nt][3] - m1);
        s0 += sc[nt][0] + sc[nt][1];
        s1 += sc[nt][2] + sc[nt][3];
    }
    #pragma unroll
    for (int o = 1; o <= 2; o <<= 1) {
        s0 += __shfl_xor_sync(0xffffffffu, s0, o);
        s1 += __shfl_xor_sync(0xffffffffu, s1, o);
    }
    const float inv0 = 1.0f / s0;
    const float inv1 = 1.0f / s1;

    float ov[8][4];
    #pragma unroll
    for (int nt = 0; nt < 8; nt++)
        #pragma unroll
        for (int r = 0; r < 4; r++)
            ov[nt][r] = 0.0f;

    const uint32_t rowV = (uint32_t)((lane & 15) * 128);
    #pragma unroll
    for (int kj = 0; kj < 12; kj++) {
        uint32_t ra0 = pack_bf16(sc[2 * kj][0] * inv0,     sc[2 * kj][1] * inv0);
        uint32_t ra1 = pack_bf16(sc[2 * kj][2] * inv1,     sc[2 * kj][3] * inv1);
        uint32_t ra2 = pack_bf16(sc[2 * kj + 1][0] * inv0, sc[2 * kj + 1][1] * inv0);
        uint32_t ra3 = pack_bf16(sc[2 * kj + 1][2] * inv1, sc[2 * kj + 1][3] * inv1);
        const uint32_t vbase = sV + (uint32_t)(kj * 16 * 128) + rowV;
        #pragma unroll
        for (int dt = 0; dt < 4; dt++) {
            const int row = kj * 16 + (lane & 15);
            const uint32_t cd = (uint32_t)(dt * 2 + (lane >> 4));
            uint32_t b0, b1, b2, b3;
            LDSM_X4_T(b0, b1, b2, b3, vbase + ((cd ^ (uint32_t)(row & 7)) << 4));
            MMA_BF16(ov[2 * dt][0], ov[2 * dt][1], ov[2 * dt][2], ov[2 * dt][3],
                     ra0, ra1, ra2, ra3, b0, b1);
            MMA_BF16(ov[2 * dt + 1][0], ov[2 * dt + 1][1], ov[2 * dt + 1][2], ov[2 * dt + 1][3],
                     ra0, ra1, ra2, ra3, b2, b3);
        }
    }

    __nv_bfloat16* O0 = O + ((size_t)b * SEQ + qi0) * DMODEL + h * HDIM;
    __nv_bfloat16* O1 = O + ((size_t)b * SEQ + qi1) * DMODEL + h * HDIM;
    #pragma unroll
    for (int nt = 0; nt < 8; nt++) {
        const int d = nt * 8 + tig * 2;
        *(uint32_t*)&O0[d] = pack_bf16(ov[nt][0], ov[nt][1]);
        *(uint32_t*)&O1[d] = pack_bf16(ov[nt][2], ov[nt][3]);
    }
}

// ---------------------------------------------------------------------------
// LayerNorm over y (gated blend already applied by the O-proj GEMM epilogue)
// ---------------------------------------------------------------------------
__global__ __launch_bounds__(256) void fused_ln(
    const float* __restrict__ Y,
    const float* __restrict__ gamma,
    const float* __restrict__ beta,
    float* __restrict__ out)
{
    const int r = blockIdx.x;
    const int t = threadIdx.x;
    const float* y = Y + (size_t)r * DMODEL;

    float v[4];
    float lsum = 0.0f, lsq = 0.0f;
    #pragma unroll
    for (int i = 0; i < 4; i++) {
        int c = t + i * 256;
        v[i] = y[c];
        lsum += v[i];
        lsq  += v[i] * v[i];
    }

    #pragma unroll
    for (int o = 16; o > 0; o >>= 1) {
        lsum += __shfl_xor_sync(0xffffffffu, lsum, o);
        lsq  += __shfl_xor_sync(0xffffffffu, lsq, o);
    }
    __shared__ float red[2][8];
    const int w = t >> 5, lane = t & 31;
    if (lane == 0) { red[0][w] = lsum; red[1][w] = lsq; }
    __syncthreads();
    float tsum = 0.0f, tsq = 0.0f;
    #pragma unroll
    for (int i = 0; i < 8; i++) { tsum += red[0][i]; tsq += red[1][i]; }

    const float mean = tsum * (1.0f / DMODEL);
    const float var  = tsq * (1.0f / DMODEL) - mean * mean;
    const float rstd = rsqrtf(var + 1e-5f);

    float* o = out + (size_t)r * DMODEL;
    #pragma unroll
    for (int i = 0; i < 4; i++) {
        int c = t + i * 256;
        o[c] = (v[i] - mean) * rstd * gamma[c] + beta[c];
    }
}

// ---------------------------------------------------------------------------
// Launch
// ---------------------------------------------------------------------------
extern "C" void kernel_launch(void* const* d_in, const int* in_sizes, int n_in,
                              void* d_out, int out_size)
{
    const float* X     = (const float*)d_in[0];
    const float* Cx    = (const float*)d_in[1];
    const float* Wq    = (const float*)d_in[2];
    const float* bq    = (const float*)d_in[3];
    const float* Wk    = (const float*)d_in[4];
    const float* bk    = (const float*)d_in[5];
    const float* Wv    = (const float*)d_in[6];
    const float* bv    = (const float*)d_in[7];
    const float* Wo    = (const float*)d_in[8];
    const float* bo    = (const float*)d_in[9];
    const float* Wg    = (const float*)d_in[10];
    const float* bg    = (const float*)d_in[11];
    const float* gamma = (const float*)d_in[12];
    const float* beta  = (const float*)d_in[13];
    float* out = (float*)d_out;

    float *g, *y;
    __nv_bfloat16 *qb, *kb, *vb, *attnb, *xb, *cxb, *wqg, *wkv, *wo;
    cudaGetSymbolAddress((void**)&g,     g_g);
    cudaGetSymbolAddress((void**)&y,     g_y);
    cudaGetSymbolAddress((void**)&qb,    g_qb);
    cudaGetSymbolAddress((void**)&kb,    g_kb);
    cudaGetSymbolAddress((void**)&vb,    g_vb);
    cudaGetSymbolAddress((void**)&attnb, g_attnb);
    cudaGetSymbolAddress((void**)&xb,    g_xb);
    cudaGetSymbolAddress((void**)&cxb,   g_cxb);
    cudaGetSymbolAddress((void**)&wqg,   g_wqg);
    cudaGetSymbolAddress((void**)&wkv,   g_wkv);
    cudaGetSymbolAddress((void**)&wo,    g_wo);

    cudaFuncSetAttribute(gemm_bf16, cudaFuncAttributeMaxDynamicSharedMemorySize, GEMM_SMEM);
    cudaFuncSetAttribute(attn_mma, cudaFuncAttributeMaxDynamicSharedMemorySize, ATTN_SMEM);

    // Fused conversions (2 launches)
    dim3 act_grid(ROWS * DMODEL / 4 / 256, 2);       // (8192, 2)
    conv_acts<<<act_grid, 256>>>((const float4*)X, (const float4*)Cx,
                                 (uint2*)xb, (uint2*)cxb);
    dim3 w_grid(DMODEL * DMODEL / 4 / 256, 5);       // (1024, 5)
    conv_weights<<<w_grid, 256>>>((const float4*)Wq, (const float4*)Wg,
                                  (const float4*)Wk, (const float4*)Wv,
                                  (const float4*)Wo,
                                  (uint2*)wqg, (uint2*)wkv, (uint2*)wo);

    // Fused projections: [Q|G] from X (q->bf16, g->f32); [K|V] from Cx (bf16)
    dim3 qg_grid(2 * DMODEL / GBN, ROWS / GBM);      // (16, 32)
    gemm_bf16<<<qg_grid, 256, GEMM_SMEM>>>(xb,  wqg, bq, bg, qb, g,  DMODEL, 1, 0,
                                           nullptr, nullptr);
    gemm_bf16<<<qg_grid, 256, GEMM_SMEM>>>(cxb, wkv, bk, bv, kb, vb, DMODEL, 1, 1,
                                           nullptr, nullptr);

    // Tensor-core windowed attention
    dim3 attn_grid(SEQ / 64, NHEAD, BATCH);          // (8, 16, 16)
    attn_mma<<<attn_grid, 128, ATTN_SMEM>>>(qb, kb, vb, attnb);

    // Output projection with fused gate+blend epilogue -> y
    dim3 o_grid(DMODEL / GBN, ROWS / GBM);           // (8, 32)
    gemm_bf16<<<o_grid, 256, GEMM_SMEM>>>(attnb, wo, bo, bo, y, y, DMODEL, 0, 0,
                                          X, g);

    // LayerNorm
    fused_ln<<<ROWS, 256>>>(y, gamma, beta, out);
}

// round 8
// speedup vs baseline: 8.0189x; 1.0005x over previous
#include <cuda_runtime.h>
#include <cuda_bf16.h>
#include <math.h>
#include <stdint.h>

// Problem constants
#define BATCH   16
#define SEQ     512
#define DMODEL  1024
#define NHEAD   16
#define HDIM    64
#define ROWS    (BATCH * SEQ)          // 8192
#define WIN     64                     // WINDOW/2
#define SCALE   0.125f                 // 64^-0.5

// ---------------------------------------------------------------------------
// Scratch (device globals: allocation-free per harness rules)
// ---------------------------------------------------------------------------
__device__ float g_g  [ROWS * DMODEL];
__device__ float g_y  [ROWS * DMODEL];          // gated blend result (pre-LN)
__device__ __nv_bfloat16 g_qb   [ROWS * DMODEL];
__device__ __nv_bfloat16 g_kb   [ROWS * DMODEL];
__device__ __nv_bfloat16 g_vb   [ROWS * DMODEL];
__device__ __nv_bfloat16 g_attnb[ROWS * DMODEL];
__device__ __nv_bfloat16 g_xb  [ROWS * DMODEL];
__device__ __nv_bfloat16 g_cxb [ROWS * DMODEL];
__device__ __nv_bfloat16 g_wqg [2 * DMODEL * DMODEL];   // [Wq; Wg]
__device__ __nv_bfloat16 g_wkv [2 * DMODEL * DMODEL];   // [Wk; Wv]
__device__ __nv_bfloat16 g_wo  [DMODEL * DMODEL];

// ---------------------------------------------------------------------------
// Helpers
// ---------------------------------------------------------------------------
__device__ __forceinline__ uint32_t smem_u32(const void* p) {
    uint32_t a;
    asm("{ .reg .u64 t; cvta.to.shared.u64 t, %1; cvt.u32.u64 %0, t; }"
        : "=r"(a) : "l"(p));
    return a;
}

__device__ __forceinline__ uint32_t pack_bf16(float lo, float hi) {
    __nv_bfloat162 h = __floats2bfloat162_rn(lo, hi);
    return *(uint32_t*)&h;
}

#define LDSM_X4(r0, r1, r2, r3, addr) \
    asm volatile("ldmatrix.sync.aligned.m8n8.x4.shared.b16 {%0,%1,%2,%3}, [%4];" \
                 : "=r"(r0), "=r"(r1), "=r"(r2), "=r"(r3) : "r"(addr))
#define LDSM_X4_T(r0, r1, r2, r3, addr) \
    asm volatile("ldmatrix.sync.aligned.m8n8.x4.trans.shared.b16 {%0,%1,%2,%3}, [%4];" \
                 : "=r"(r0), "=r"(r1), "=r"(r2), "=r"(r3) : "r"(addr))
#define MMA_BF16(c0, c1, c2, c3, a0, a1, a2, a3, b0, b1) \
    asm volatile("mma.sync.aligned.m16n8k16.row.col.f32.bf16.bf16.f32 " \
                 "{%0,%1,%2,%3}, {%4,%5,%6,%7}, {%8,%9}, {%0,%1,%2,%3};" \
                 : "+f"(c0), "+f"(c1), "+f"(c2), "+f"(c3) \
                 : "r"(a0), "r"(a1), "r"(a2), "r"(a3), "r"(b0), "r"(b1))

// ---------------------------------------------------------------------------
// Fused f32->bf16 conversions
// ---------------------------------------------------------------------------
__global__ __launch_bounds__(256) void conv_acts(
    const float4* __restrict__ X, const float4* __restrict__ Cx,
    uint2* __restrict__ xb, uint2* __restrict__ cxb)
{
    int i = blockIdx.x * 256 + threadIdx.x;          // 0 .. 2M-1
    const float4* src = blockIdx.y ? Cx : X;
    uint2* dst = blockIdx.y ? cxb : xb;
    float4 v = src[i];
    uint2 o;
    o.x = pack_bf16(v.x, v.y);
    o.y = pack_bf16(v.z, v.w);
    dst[i] = o;
}

__global__ __launch_bounds__(256) void conv_weights(
    const float4* __restrict__ Wq, const float4* __restrict__ Wg,
    const float4* __restrict__ Wk, const float4* __restrict__ Wv,
    const float4* __restrict__ Wo,
    uint2* __restrict__ wqg, uint2* __restrict__ wkv, uint2* __restrict__ wo)
{
    int i = blockIdx.x * 256 + threadIdx.x;          // 0 .. 256K-1
    int s = blockIdx.y;                              // 0..4
    const float4* src = (s == 0) ? Wq : (s == 1) ? Wg : (s == 2) ? Wk
                       : (s == 3) ? Wv : Wo;
    uint2* dst = (s == 0) ? wqg
               : (s == 1) ? (wqg + DMODEL * DMODEL / 4)
               : (s == 2) ? wkv
               : (s == 3) ? (wkv + DMODEL * DMODEL / 4)
               : wo;
    float4 v = src[i];
    uint2 o;
    o.x = pack_bf16(v.x, v.y);
    o.y = pack_bf16(v.z, v.w);
    dst[i] = o;
}

// ---------------------------------------------------------------------------
// bf16 mma GEMM v2: C[M,Ntot] = A[M,K]*W[Ntot,K]^T + bias, split at nsplit.
// CTA 256x128, 256 threads (8 warps 4x2), warp tile 64x64, BK=64, 4 stages.
// Optional fused gated-blend epilogue (epiX/epiG non-null):
//   y = 0.5*X + 0.5*sigmoid(G)*(acc+bias)
// ---------------------------------------------------------------------------
#define GBM 256
#define GBN 128
#define GBK 64
#define GSTAGES 4
#define GITERS (DMODEL / GBK)                  // 16
#define TILE_A_BYTES (GBM * GBK * 2)           // 32768
#define TILE_B_BYTES (GBN * GBK * 2)           // 16384
#define STAGE_BYTES (TILE_A_BYTES + TILE_B_BYTES)  // 49152
#define GEMM_SMEM   (GSTAGES * STAGE_BYTES)        // 196608

__device__ __forceinline__ void cp_stage(uint32_t sA, uint32_t sB,
                                         const __nv_bfloat16* __restrict__ Arow,
                                         const __nv_bfloat16* __restrict__ Wrow,
                                         int k0, int t)
{
    #pragma unroll
    for (int i = 0; i < 12; i++) {
        int idx = i * 256 + t;                    // 0..3071
        int row = idx >> 3;                       // 0..383 (A:0-255, B:256-383)
        int c   = idx & 7;
        uint32_t soff = ((uint32_t)c ^ (uint32_t)(row & 7)) << 4;
        if (row < GBM) {
            const __nv_bfloat16* ga = Arow + (size_t)row * DMODEL + k0 + c * 8;
            asm volatile("cp.async.cg.shared.global [%0], [%1], 16;"
                         :: "r"(sA + (uint32_t)row * 128 + soff), "l"(ga));
        } else {
            int rb = row - GBM;
            const __nv_bfloat16* gb = Wrow + (size_t)rb * DMODEL + k0 + c * 8;
            asm volatile("cp.async.cg.shared.global [%0], [%1], 16;"
                         :: "r"(sB + (uint32_t)rb * 128 + soff), "l"(gb));
        }
    }
}

__global__ __launch_bounds__(256, 1)
void gemm_bf16(const __nv_bfloat16* __restrict__ A,
               const __nv_bfloat16* __restrict__ W,
               const float* __restrict__ bias0,
               const float* __restrict__ bias1,
               void* __restrict__ C0,
               void* __restrict__ C1,
               int nsplit, int obf0, int obf1,
               const float* __restrict__ epiX,
               const float* __restrict__ epiG)
{
    extern __shared__ char smem[];
    const uint32_t sb = smem_u32(smem);
    const int t = threadIdx.x;
    const int bm = blockIdx.y * GBM;
    const int bn = blockIdx.x * GBN;

    const int lane = t & 31;
    const int warp = t >> 5;
    const int grp  = lane >> 2;
    const int tig  = lane & 3;
    const int wm   = warp >> 1;        // 0..3
    const int wn   = warp & 1;         // 0..1
    const int m_base = wm * 64;
    const int n_base = wn * 64;

    const bool hiHalf = (bn >= nsplit);
    void* Cx = hiHalf ? C1 : C0;
    const float* biasx = hiHalf ? bias1 : bias0;
    const int bnl = hiHalf ? (bn - nsplit) : bn;
    const int obf = hiHalf ? obf1 : obf0;

    const __nv_bfloat16* Arow = A + (size_t)bm * DMODEL;
    const __nv_bfloat16* Wrow = W + (size_t)bn * DMODEL;

    const int s7 = lane & 7;
    const int hi16 = lane >> 4;
    const int cb   = (lane >> 3) & 1;
    uint32_t rbA[4], rbB[4];
    #pragma unroll
    for (int fi = 0; fi < 4; fi++)
        rbA[fi] = (uint32_t)((m_base + fi * 16 + (lane & 15)) * 128);
    #pragma unroll
    for (int pr = 0; pr < 4; pr++)
        rbB[pr] = (uint32_t)((n_base + pr * 16 + ((lane >> 4) << 3) + (lane & 7)) * 128);

    float acc[4][8][4];
    #pragma unroll
    for (int fi = 0; fi < 4; fi++)
        #pragma unroll
        for (int fj = 0; fj < 8; fj++)
            #pragma unroll
            for (int r = 0; r < 4; r++)
                acc[fi][fj][r] = 0.0f;

    #pragma unroll
    for (int s = 0; s < GSTAGES - 1; s++) {
        cp_stage(sb + s * STAGE_BYTES, sb + s * STAGE_BYTES + TILE_A_BYTES,
                 Arow, Wrow, s * GBK, t);
        asm volatile("cp.async.commit_group;" ::: "memory");
    }

    for (int it = 0; it < GITERS; it++) {
        asm volatile("cp.async.wait_group 2;" ::: "memory");
        __syncthreads();

        const int ps = it + GSTAGES - 1;
        if (ps < GITERS) {
            const int s = ps % GSTAGES;
            cp_stage(sb + s * STAGE_BYTES, sb + s * STAGE_BYTES + TILE_A_BYTES,
                     Arow, Wrow, ps * GBK, t);
        }
        asm volatile("cp.async.commit_group;" ::: "memory");

        const uint32_t sA = sb + (it % GSTAGES) * STAGE_BYTES;
        const uint32_t sB = sA + TILE_A_BYTES;

        #pragma unroll
        for (int ks = 0; ks < 4; ks++) {
            const uint32_t coA = (uint32_t)(((2 * ks + hi16) ^ s7) << 4);
            const uint32_t coB = (uint32_t)(((2 * ks + cb)   ^ s7) << 4);

            uint32_t a[4][4];
            #pragma unroll
            for (int fi = 0; fi < 4; fi++)
                LDSM_X4(a[fi][0], a[fi][1], a[fi][2], a[fi][3], sA + rbA[fi] + coA);

            uint32_t b[4][4];
            #pragma unroll
            for (int pr = 0; pr < 4; pr++)
                LDSM_X4(b[pr][0], b[pr][1], b[pr][2], b[pr][3], sB + rbB[pr] + coB);

            #pragma unroll
            for (int fi = 0; fi < 4; fi++)
                #pragma unroll
                for (int fj = 0; fj < 8; fj++) {
                    const int pr = fj >> 1, hf = (fj & 1) << 1;
                    MMA_BF16(acc[fi][fj][0], acc[fi][fj][1], acc[fi][fj][2], acc[fi][fj][3],
                             a[fi][0], a[fi][1], a[fi][2], a[fi][3],
                             b[pr][hf], b[pr][hf + 1]);
                }
        }
    }

    // Epilogue
    #pragma unroll
    for (int fi = 0; fi < 4; fi++) {
        const int m0 = bm + m_base + fi * 16 + grp;
        #pragma unroll
        for (int fj = 0; fj < 8; fj++) {
            const int n = bnl + n_base + fj * 8 + tig * 2;
            const float2 bv = *(const float2*)&biasx[n];
            float v00 = acc[fi][fj][0] + bv.x;
            float v01 = acc[fi][fj][1] + bv.y;
            float v10 = acc[fi][fj][2] + bv.x;
            float v11 = acc[fi][fj][3] + bv.y;
            const size_t i0 = (size_t)m0 * DMODEL + n;
            const size_t i1 = (size_t)(m0 + 8) * DMODEL + n;
            if (epiX) {
                // gated blend: y = 0.5*X + 0.5*sigmoid(G)*proj
                float2 x0 = *(const float2*)&epiX[i0];
                float2 x1 = *(const float2*)&epiX[i1];
                float2 g0 = *(const float2*)&epiG[i0];
                float2 g1 = *(const float2*)&epiG[i1];
                v00 = 0.5f * x0.x + 0.5f * v00 / (1.0f + __expf(-g0.x));
                v01 = 0.5f * x0.y + 0.5f * v01 / (1.0f + __expf(-g0.y));
                v10 = 0.5f * x1.x + 0.5f * v10 / (1.0f + __expf(-g1.x));
                v11 = 0.5f * x1.y + 0.5f * v11 / (1.0f + __expf(-g1.y));
            }
            if (obf) {
                __nv_bfloat16* cp = (__nv_bfloat16*)Cx;
                *(uint32_t*)&cp[i0] = pack_bf16(v00, v01);
                *(uint32_t*)&cp[i1] = pack_bf16(v10, v11);
            } else {
                float* cp = (float*)Cx;
                *(float2*)&cp[i0] = make_float2(v00, v01);
                *(float2*)&cp[i1] = make_float2(v10, v11);
            }
        }
    }
}

// ---------------------------------------------------------------------------
// Windowed attention on tensor cores (R6-proven).
// ---------------------------------------------------------------------------
#define KRANGE 192
#define NJT    24
#define ATTN_SMEM ((64 + KRANGE + KRANGE) * 128)   // 57344 B

__global__ __launch_bounds__(128)
void attn_mma(const __nv_bfloat16* __restrict__ Q,
              const __nv_bfloat16* __restrict__ K,
              const __nv_bfloat16* __restrict__ V,
              __nv_bfloat16* __restrict__ O)
{
    extern __shared__ char smem[];
    const uint32_t sQ = smem_u32(smem);
    const uint32_t sK = sQ + 64 * 128;
    const uint32_t sV = sK + KRANGE * 128;

    const int qt   = blockIdx.x;
    const int h    = blockIdx.y;
    const int b    = blockIdx.z;
    const int t    = threadIdx.x;
    const int lane = t & 31;
    const int w    = t >> 5;
    const int grp  = lane >> 2;
    const int tig  = lane & 3;

    const int q0    = qt * 64;
    const int kbase = q0 - WIN;

    const __nv_bfloat16* Qg = Q + ((size_t)b * SEQ) * DMODEL + h * HDIM;
    const __nv_bfloat16* Kg = K + ((size_t)b * SEQ) * DMODEL + h * HDIM;
    const __nv_bfloat16* Vg = V + ((size_t)b * SEQ) * DMODEL + h * HDIM;

    for (int i = t; i < 64 * 8; i += 128) {
        int row = i >> 3, c = i & 7;
        uint32_t dst = sQ + row * 128 + ((c ^ (row & 7)) << 4);
        const __nv_bfloat16* src = Qg + (size_t)(q0 + row) * DMODEL + c * 8;
        asm volatile("cp.async.cg.shared.global [%0], [%1], 16;" :: "r"(dst), "l"(src));
    }
    for (int i = t; i < KRANGE * 8; i += 128) {
        int row = i >> 3, c = i & 7;
        int jg = kbase + row;
        uint32_t off = row * 128 + ((c ^ (row & 7)) << 4);
        if ((unsigned)jg < (unsigned)SEQ) {
            const __nv_bfloat16* srck = Kg + (size_t)jg * DMODEL + c * 8;
            const __nv_bfloat16* srcv = Vg + (size_t)jg * DMODEL + c * 8;
            asm volatile("cp.async.cg.shared.global [%0], [%1], 16;" :: "r"(sK + off), "l"(srck));
            asm volatile("cp.async.cg.shared.global [%0], [%1], 16;" :: "r"(sV + off), "l"(srcv));
        } else {
            asm volatile("st.shared.v4.b32 [%0], {%1,%1,%1,%1};" :: "r"(sK + off), "r"(0u));
            asm volatile("st.shared.v4.b32 [%0], {%1,%1,%1,%1};" :: "r"(sV + off), "r"(0u));
        }
    }
    asm volatile("cp.async.commit_group;" ::: "memory");
    asm volatile("cp.async.wait_group 0;" ::: "memory");
    __syncthreads();

    const int s7 = lane & 7;
    const int m_base = w * 16;
    const uint32_t rowA = (uint32_t)((m_base + (lane & 15)) * 128);
    const int hi16 = lane >> 4;
    const uint32_t rowBoff = (uint32_t)((((lane >> 4) << 3) + (lane & 7)) * 128);
    const int cb = (lane >> 3) & 1;

    float sc[NJT][4];
    #pragma unroll
    for (int nt = 0; nt < NJT; nt++)
        #pragma unroll
        for (int r = 0; r < 4; r++)
            sc[nt][r] = 0.0f;

    #pragma unroll
    for (int ks = 0; ks < 4; ks++) {
        const uint32_t coA = (uint32_t)(((2 * ks + hi16) ^ s7) << 4);
        const uint32_t coB = (uint32_t)(((2 * ks + cb) ^ s7) << 4);
        uint32_t a0, a1, a2, a3;
        LDSM_X4(a0, a1, a2, a3, sQ + rowA + coA);
        #pragma unroll
        for (int jt = 0; jt < 12; jt++) {
            uint32_t b0, b1, b2, b3;
            LDSM_X4(b0, b1, b2, b3, sK + (uint32_t)(jt * 16 * 128) + rowBoff + coB);
            MMA_BF16(sc[2 * jt][0], sc[2 * jt][1], sc[2 * jt][2], sc[2 * jt][3],
                     a0, a1, a2, a3, b0, b1);
            MMA_BF16(sc[2 * jt + 1][0], sc[2 * jt + 1][1], sc[2 * jt + 1][2], sc[2 * jt + 1][3],
                     a0, a1, a2, a3, b2, b3);
        }
    }

    const int qi0 = q0 + m_base + grp;
    const int qi1 = qi0 + 8;
    #pragma unroll
    for (int nt = 0; nt < NJT; nt++) {
        const int jg0 = kbase + nt * 8 + tig * 2;
        const int jg1 = jg0 + 1;
        bool v00 = ((unsigned)jg0 < (unsigned)SEQ) && ((unsigned)(qi0 - jg0 + WIN) <= 2u * WIN);
        bool v01 = ((unsigned)jg1 < (unsigned)SEQ) && ((unsigned)(qi0 - jg1 + WIN) <= 2u * WIN);
        bool v10 = ((unsigned)jg0 < (unsigned)SEQ) && ((unsigned)(qi1 - jg0 + WIN) <= 2u * WIN);
        bool v11 = ((unsigned)jg1 < (unsigned)SEQ) && ((unsigned)(qi1 - jg1 + WIN) <= 2u * WIN);
        sc[nt][0] = v00 ? sc[nt][0] * SCALE : -1e30f;
        sc[nt][1] = v01 ? sc[nt][1] * SCALE : -1e30f;
        sc[nt][2] = v10 ? sc[nt][2] * SCALE : -1e30f;
        sc[nt][3] = v11 ? sc[nt][3] * SCALE : -1e30f;
    }

    float m0 = -1e30f, m1 = -1e30f;
    #pragma unroll
    for (int nt = 0; nt < NJT; nt++) {
        m0 = fmaxf(m0, fmaxf(sc[nt][0], sc[nt][1]));
        m1 = fmaxf(m1, fmaxf(sc[nt][2], sc[nt][3]));
    }
    #pragma unroll
    for (int o = 1; o <= 2; o <<= 1) {
        m0 = fmaxf(m0, __shfl_xor_sync(0xffffffffu, m0, o));
        m1 = fmaxf(m1, __shfl_xor_sync(0xffffffffu, m1, o));
    }
    float s0 = 0.0f, s1 = 0.0f;
    #pragma unroll
    for (int nt = 0; nt < NJT; nt++) {
        sc[nt][0] = __expf(sc[nt][0] - m0);
        sc[nt][1] = __expf(sc[nt][1] - m0);
        sc[nt][2] = __expf(sc[nt][2] - m1);
        sc[nt][3] = __expf(sc[nt][3] - m1);
        s0 += sc[nt][0] + sc[nt][1];
        s1 += sc[nt][2] + sc[nt][3];
    }
    #pragma unroll
    for (int o = 1; o <= 2; o <<= 1) {
        s0 += __shfl_xor_sync(0xffffffffu, s0, o);
        s1 += __shfl_xor_sync(0xffffffffu, s1, o);
    }
    const float inv0 = 1.0f / s0;
    const float inv1 = 1.0f / s1;

    float ov[8][4];
    #pragma unroll
    for (int nt = 0; nt < 8; nt++)
        #pragma unroll
        for (int r = 0; r < 4; r++)
            ov[nt][r] = 0.0f;

    const uint32_t rowV = (uint32_t)((lane & 15) * 128);
    #pragma unroll
    for (int kj = 0; kj < 12; kj++) {
        uint32_t ra0 = pack_bf16(sc[2 * kj][0] * inv0,     sc[2 * kj][1] * inv0);
        uint32_t ra1 = pack_bf16(sc[2 * kj][2] * inv1,     sc[2 * kj][3] * inv1);
        uint32_t ra2 = pack_bf16(sc[2 * kj + 1][0] * inv0, sc[2 * kj + 1][1] * inv0);
        uint32_t ra3 = pack_bf16(sc[2 * kj + 1][2] * inv1, sc[2 * kj + 1][3] * inv1);
        const uint32_t vbase = sV + (uint32_t)(kj * 16 * 128) + rowV;
        #pragma unroll
        for (int dt = 0; dt < 4; dt++) {
            const int row = kj * 16 + (lane & 15);
            const uint32_t cd = (uint32_t)(dt * 2 + (lane >> 4));
            uint32_t b0, b1, b2, b3;
            LDSM_X4_T(b0, b1, b2, b3, vbase + ((cd ^ (uint32_t)(row & 7)) << 4));
            MMA_BF16(ov[2 * dt][0], ov[2 * dt][1], ov[2 * dt][2], ov[2 * dt][3],
                     ra0, ra1, ra2, ra3, b0, b1);
            MMA_BF16(ov[2 * dt + 1][0], ov[2 * dt + 1][1], ov[2 * dt + 1][2], ov[2 * dt + 1][3],
                     ra0, ra1, ra2, ra3, b2, b3);
        }
    }

    __nv_bfloat16* O0 = O + ((size_t)b * SEQ + qi0) * DMODEL + h * HDIM;
    __nv_bfloat16* O1 = O + ((size_t)b * SEQ + qi1) * DMODEL + h * HDIM;
    #pragma unroll
    for (int nt = 0; nt < 8; nt++) {
        const int d = nt * 8 + tig * 2;
        *(uint32_t*)&O0[d] = pack_bf16(ov[nt][0], ov[nt][1]);
        *(uint32_t*)&O1[d] = pack_bf16(ov[nt][2], ov[nt][3]);
    }
}

// ---------------------------------------------------------------------------
// LayerNorm over y (gated blend already applied by the O-proj GEMM epilogue)
// ---------------------------------------------------------------------------
__global__ __launch_bounds__(256) void fused_ln(
    const float* __restrict__ Y,
    const float* __restrict__ gamma,
    const float* __restrict__ beta,
    float* __restrict__ out)
{
    const int r = blockIdx.x;
    const int t = threadIdx.x;
    const float* y = Y + (size_t)r * DMODEL;

    float v[4];
    float lsum = 0.0f, lsq = 0.0f;
    #pragma unroll
    for (int i = 0; i < 4; i++) {
        int c = t + i * 256;
        v[i] = y[c];
        lsum += v[i];
        lsq  += v[i] * v[i];
    }

    #pragma unroll
    for (int o = 16; o > 0; o >>= 1) {
        lsum += __shfl_xor_sync(0xffffffffu, lsum, o);
        lsq  += __shfl_xor_sync(0xffffffffu, lsq, o);
    }
    __shared__ float red[2][8];
    const int w = t >> 5, lane = t & 31;
    if (lane == 0) { red[0][w] = lsum; red[1][w] = lsq; }
    __syncthreads();
    float tsum = 0.0f, tsq = 0.0f;
    #pragma unroll
    for (int i = 0; i < 8; i++) { tsum += red[0][i]; tsq += red[1][i]; }

    const float mean = tsum * (1.0f / DMODEL);
    const float var  = tsq * (1.0f / DMODEL) - mean * mean;
    const float rstd = rsqrtf(var + 1e-5f);

    float* o = out + (size_t)r * DMODEL;
    #pragma unroll
    for (int i = 0; i < 4; i++) {
        int c = t + i * 256;
        o[c] = (v[i] - mean) * rstd * gamma[c] + beta[c];
    }
}

// ---------------------------------------------------------------------------
// Launch
// ---------------------------------------------------------------------------
extern "C" void kernel_launch(void* const* d_in, const int* in_sizes, int n_in,
                              void* d_out, int out_size)
{
    const float* X     = (const float*)d_in[0];
    const float* Cx    = (const float*)d_in[1];
    const float* Wq    = (const float*)d_in[2];
    const float* bq    = (const float*)d_in[3];
    const float* Wk    = (const float*)d_in[4];
    const float* bk    = (const float*)d_in[5];
    const float* Wv    = (const float*)d_in[6];
    const float* bv    = (const float*)d_in[7];
    const float* Wo    = (const float*)d_in[8];
    const float* bo    = (const float*)d_in[9];
    const float* Wg    = (const float*)d_in[10];
    const float* bg    = (const float*)d_in[11];
    const float* gamma = (const float*)d_in[12];
    const float* beta  = (const float*)d_in[13];
    float* out = (float*)d_out;

    float *g, *y;
    __nv_bfloat16 *qb, *kb, *vb, *attnb, *xb, *cxb, *wqg, *wkv, *wo;
    cudaGetSymbolAddress((void**)&g,     g_g);
    cudaGetSymbolAddress((void**)&y,     g_y);
    cudaGetSymbolAddress((void**)&qb,    g_qb);
    cudaGetSymbolAddress((void**)&kb,    g_kb);
    cudaGetSymbolAddress((void**)&vb,    g_vb);
    cudaGetSymbolAddress((void**)&attnb, g_attnb);
    cudaGetSymbolAddress((void**)&xb,    g_xb);
    cudaGetSymbolAddress((void**)&cxb,   g_cxb);
    cudaGetSymbolAddress((void**)&wqg,   g_wqg);
    cudaGetSymbolAddress((void**)&wkv,   g_wkv);
    cudaGetSymbolAddress((void**)&wo,    g_wo);

    cudaFuncSetAttribute(gemm_bf16, cudaFuncAttributeMaxDynamicSharedMemorySize, GEMM_SMEM);
    cudaFuncSetAttribute(attn_mma, cudaFuncAttributeMaxDynamicSharedMemorySize, ATTN_SMEM);

    // Fused conversions (2 launches)
    dim3 act_grid(ROWS * DMODEL / 4 / 256, 2);       // (8192, 2)
    conv_acts<<<act_grid, 256>>>((const float4*)X, (const float4*)Cx,
                                 (uint2*)xb, (uint2*)cxb);
    dim3 w_grid(DMODEL * DMODEL / 4 / 256, 5);       // (1024, 5)
    conv_weights<<<w_grid, 256>>>((const float4*)Wq, (const float4*)Wg,
                                  (const float4*)Wk, (const float4*)Wv,
                                  (const float4*)Wo,
                                  (uint2*)wqg, (uint2*)wkv, (uint2*)wo);

    // Fused projections: [Q|G] from X (q->bf16, g->f32); [K|V] from Cx (bf16)
    dim3 qg_grid(2 * DMODEL / GBN, ROWS / GBM);      // (16, 32)
    gemm_bf16<<<qg_grid, 256, GEMM_SMEM>>>(xb,  wqg, bq, bg, qb, g,  DMODEL, 1, 0,
                                           nullptr, nullptr);
    gemm_bf16<<<qg_grid, 256, GEMM_SMEM>>>(cxb, wkv, bk, bv, kb, vb, DMODEL, 1, 1,
                                           nullptr, nullptr);

    // Tensor-core windowed attention
    dim3 attn_grid(SEQ / 64, NHEAD, BATCH);          // (8, 16, 16)
    attn_mma<<<attn_grid, 128, ATTN_SMEM>>>(qb, kb, vb, attnb);

    // Output projection with fused gate+blend epilogue -> y
    dim3 o_grid(DMODEL / GBN, ROWS / GBM);           // (8, 32)
    gemm_bf16<<<o_grid, 256, GEMM_SMEM>>>(attnb, wo, bo, bo, y, y, DMODEL, 0, 0,
                                          X, g);

    // LayerNorm
    fused_ln<<<ROWS, 256>>>(y, gamma, beta, out);
}

// round 9
// speedup vs baseline: 8.0343x; 1.0019x over previous
#include <cuda_runtime.h>
#include <cuda_bf16.h>
#include <math.h>
#include <stdint.h>

// Problem constants
#define BATCH   16
#define SEQ     512
#define DMODEL  1024
#define NHEAD   16
#define HDIM    64
#define ROWS    (BATCH * SEQ)          // 8192
#define WIN     64                     // WINDOW/2
#define SCALE   0.125f                 // 64^-0.5

// ---------------------------------------------------------------------------
// Scratch (device globals: allocation-free per harness rules)
// ---------------------------------------------------------------------------
__device__ float g_g  [ROWS * DMODEL];
__device__ float g_y  [ROWS * DMODEL];          // gated blend result (pre-LN)
__device__ __nv_bfloat16 g_qb   [ROWS * DMODEL];
__device__ __nv_bfloat16 g_kb   [ROWS * DMODEL];
__device__ __nv_bfloat16 g_vb   [ROWS * DMODEL];
__device__ __nv_bfloat16 g_attnb[ROWS * DMODEL];
__device__ __nv_bfloat16 g_xb  [ROWS * DMODEL];
__device__ __nv_bfloat16 g_cxb [ROWS * DMODEL];
__device__ __nv_bfloat16 g_wqg [2 * DMODEL * DMODEL];   // [Wq; Wg]
__device__ __nv_bfloat16 g_wkv [2 * DMODEL * DMODEL];   // [Wk; Wv]
__device__ __nv_bfloat16 g_wo  [DMODEL * DMODEL];

// ---------------------------------------------------------------------------
// Helpers
// ---------------------------------------------------------------------------
__device__ __forceinline__ uint32_t smem_u32(const void* p) {
    uint32_t a;
    asm("{ .reg .u64 t; cvta.to.shared.u64 t, %1; cvt.u32.u64 %0, t; }"
        : "=r"(a) : "l"(p));
    return a;
}

__device__ __forceinline__ uint32_t pack_bf16(float lo, float hi) {
    __nv_bfloat162 h = __floats2bfloat162_rn(lo, hi);
    return *(uint32_t*)&h;
}

#define LDSM_X4(r0, r1, r2, r3, addr) \
    asm volatile("ldmatrix.sync.aligned.m8n8.x4.shared.b16 {%0,%1,%2,%3}, [%4];" \
                 : "=r"(r0), "=r"(r1), "=r"(r2), "=r"(r3) : "r"(addr))
#define LDSM_X4_T(r0, r1, r2, r3, addr) \
    asm volatile("ldmatrix.sync.aligned.m8n8.x4.trans.shared.b16 {%0,%1,%2,%3}, [%4];" \
                 : "=r"(r0), "=r"(r1), "=r"(r2), "=r"(r3) : "r"(addr))
#define MMA_BF16(c0, c1, c2, c3, a0, a1, a2, a3, b0, b1) \
    asm volatile("mma.sync.aligned.m16n8k16.row.col.f32.bf16.bf16.f32 " \
                 "{%0,%1,%2,%3}, {%4,%5,%6,%7}, {%8,%9}, {%0,%1,%2,%3};" \
                 : "+f"(c0), "+f"(c1), "+f"(c2), "+f"(c3) \
                 : "r"(a0), "r"(a1), "r"(a2), "r"(a3), "r"(b0), "r"(b1))

// ---------------------------------------------------------------------------
// Fused f32->bf16 conversions
// ---------------------------------------------------------------------------
__global__ __launch_bounds__(256) void conv_acts(
    const float4* __restrict__ X, const float4* __restrict__ Cx,
    uint2* __restrict__ xb, uint2* __restrict__ cxb)
{
    int i = blockIdx.x * 256 + threadIdx.x;          // 0 .. 2M-1
    const float4* src = blockIdx.y ? Cx : X;
    uint2* dst = blockIdx.y ? cxb : xb;
    float4 v = src[i];
    uint2 o;
    o.x = pack_bf16(v.x, v.y);
    o.y = pack_bf16(v.z, v.w);
    dst[i] = o;
}

__global__ __launch_bounds__(256) void conv_weights(
    const float4* __restrict__ Wq, const float4* __restrict__ Wg,
    const float4* __restrict__ Wk, const float4* __restrict__ Wv,
    const float4* __restrict__ Wo,
    uint2* __restrict__ wqg, uint2* __restrict__ wkv, uint2* __restrict__ wo)
{
    int i = blockIdx.x * 256 + threadIdx.x;          // 0 .. 256K-1
    int s = blockIdx.y;                              // 0..4
    const float4* src = (s == 0) ? Wq : (s == 1) ? Wg : (s == 2) ? Wk
                       : (s == 3) ? Wv : Wo;
    uint2* dst = (s == 0) ? wqg
               : (s == 1) ? (wqg + DMODEL * DMODEL / 4)
               : (s == 2) ? wkv
               : (s == 3) ? (wkv + DMODEL * DMODEL / 4)
               : wo;
    float4 v = src[i];
    uint2 o;
    o.x = pack_bf16(v.x, v.y);
    o.y = pack_bf16(v.z, v.w);
    dst[i] = o;
}

// ---------------------------------------------------------------------------
// bf16 mma GEMM v2: C[M,Ntot] = A[M,K]*W[Ntot,K]^T + bias, split at nsplit.
// CTA 256x128, 256 threads (8 warps 4x2), warp tile 64x64, BK=64, 4 stages.
// Optional fused gated-blend epilogue (epiX/epiG non-null):
//   y = 0.5*X + 0.5*sigmoid(G)*(acc+bias)
// ---------------------------------------------------------------------------
#define GBM 256
#define GBN 128
#define GBK 64
#define GSTAGES 4
#define GITERS (DMODEL / GBK)                  // 16
#define TILE_A_BYTES (GBM * GBK * 2)           // 32768
#define TILE_B_BYTES (GBN * GBK * 2)           // 16384
#define STAGE_BYTES (TILE_A_BYTES + TILE_B_BYTES)  // 49152
#define GEMM_SMEM   (GSTAGES * STAGE_BYTES)        // 196608

__device__ __forceinline__ void cp_stage(uint32_t sA, uint32_t sB,
                                         const __nv_bfloat16* __restrict__ Arow,
                                         const __nv_bfloat16* __restrict__ Wrow,
                                         int k0, int t)
{
    #pragma unroll
    for (int i = 0; i < 12; i++) {
        int idx = i * 256 + t;                    // 0..3071
        int row = idx >> 3;                       // 0..383 (A:0-255, B:256-383)
        int c   = idx & 7;
        uint32_t soff = ((uint32_t)c ^ (uint32_t)(row & 7)) << 4;
        if (row < GBM) {
            const __nv_bfloat16* ga = Arow + (size_t)row * DMODEL + k0 + c * 8;
            asm volatile("cp.async.cg.shared.global [%0], [%1], 16;"
                         :: "r"(sA + (uint32_t)row * 128 + soff), "l"(ga));
        } else {
            int rb = row - GBM;
            const __nv_bfloat16* gb = Wrow + (size_t)rb * DMODEL + k0 + c * 8;
            asm volatile("cp.async.cg.shared.global [%0], [%1], 16;"
                         :: "r"(sB + (uint32_t)rb * 128 + soff), "l"(gb));
        }
    }
}

__global__ __launch_bounds__(256, 1)
void gemm_bf16(const __nv_bfloat16* __restrict__ A,
               const __nv_bfloat16* __restrict__ W,
               const float* __restrict__ bias0,
               const float* __restrict__ bias1,
               void* __restrict__ C0,
               void* __restrict__ C1,
               int nsplit, int obf0, int obf1,
               const float* __restrict__ epiX,
               const float* __restrict__ epiG)
{
    extern __shared__ char smem[];
    const uint32_t sb = smem_u32(smem);
    const int t = threadIdx.x;
    const int bm = blockIdx.y * GBM;
    const int bn = blockIdx.x * GBN;

    const int lane = t & 31;
    const int warp = t >> 5;
    const int grp  = lane >> 2;
    const int tig  = lane & 3;
    const int wm   = warp >> 1;        // 0..3
    const int wn   = warp & 1;         // 0..1
    const int m_base = wm * 64;
    const int n_base = wn * 64;

    const bool hiHalf = (bn >= nsplit);
    void* Cx = hiHalf ? C1 : C0;
    const float* biasx = hiHalf ? bias1 : bias0;
    const int bnl = hiHalf ? (bn - nsplit) : bn;
    const int obf = hiHalf ? obf1 : obf0;

    const __nv_bfloat16* Arow = A + (size_t)bm * DMODEL;
    const __nv_bfloat16* Wrow = W + (size_t)bn * DMODEL;

    const int s7 = lane & 7;
    const int hi16 = lane >> 4;
    const int cb   = (lane >> 3) & 1;
    uint32_t rbA[4], rbB[4];
    #pragma unroll
    for (int fi = 0; fi < 4; fi++)
        rbA[fi] = (uint32_t)((m_base + fi * 16 + (lane & 15)) * 128);
    #pragma unroll
    for (int pr = 0; pr < 4; pr++)
        rbB[pr] = (uint32_t)((n_base + pr * 16 + ((lane >> 4) << 3) + (lane & 7)) * 128);

    float acc[4][8][4];
    #pragma unroll
    for (int fi = 0; fi < 4; fi++)
        #pragma unroll
        for (int fj = 0; fj < 8; fj++)
            #pragma unroll
            for (int r = 0; r < 4; r++)
                acc[fi][fj][r] = 0.0f;

    #pragma unroll
    for (int s = 0; s < GSTAGES - 1; s++) {
        cp_stage(sb + s * STAGE_BYTES, sb + s * STAGE_BYTES + TILE_A_BYTES,
                 Arow, Wrow, s * GBK, t);
        asm volatile("cp.async.commit_group;" ::: "memory");
    }

    for (int it = 0; it < GITERS; it++) {
        asm volatile("cp.async.wait_group 2;" ::: "memory");
        __syncthreads();

        const int ps = it + GSTAGES - 1;
        if (ps < GITERS) {
            const int s = ps % GSTAGES;
            cp_stage(sb + s * STAGE_BYTES, sb + s * STAGE_BYTES + TILE_A_BYTES,
                     Arow, Wrow, ps * GBK, t);
        }
        asm volatile("cp.async.commit_group;" ::: "memory");

        const uint32_t sA = sb + (it % GSTAGES) * STAGE_BYTES;
        const uint32_t sB = sA + TILE_A_BYTES;

        #pragma unroll
        for (int ks = 0; ks < 4; ks++) {
            const uint32_t coA = (uint32_t)(((2 * ks + hi16) ^ s7) << 4);
            const uint32_t coB = (uint32_t)(((2 * ks + cb)   ^ s7) << 4);

            uint32_t a[4][4];
            #pragma unroll
            for (int fi = 0; fi < 4; fi++)
                LDSM_X4(a[fi][0], a[fi][1], a[fi][2], a[fi][3], sA + rbA[fi] + coA);

            uint32_t b[4][4];
            #pragma unroll
            for (int pr = 0; pr < 4; pr++)
                LDSM_X4(b[pr][0], b[pr][1], b[pr][2], b[pr][3], sB + rbB[pr] + coB);

            #pragma unroll
            for (int fi = 0; fi < 4; fi++)
                #pragma unroll
                for (int fj = 0; fj < 8; fj++) {
                    const int pr = fj >> 1, hf = (fj & 1) << 1;
                    MMA_BF16(acc[fi][fj][0], acc[fi][fj][1], acc[fi][fj][2], acc[fi][fj][3],
                             a[fi][0], a[fi][1], a[fi][2], a[fi][3],
                             b[pr][hf], b[pr][hf + 1]);
                }
        }
    }

    // Epilogue
    #pragma unroll
    for (int fi = 0; fi < 4; fi++) {
        const int m0 = bm + m_base + fi * 16 + grp;
        #pragma unroll
        for (int fj = 0; fj < 8; fj++) {
            const int n = bnl + n_base + fj * 8 + tig * 2;
            const float2 bv = *(const float2*)&biasx[n];
            float v00 = acc[fi][fj][0] + bv.x;
            float v01 = acc[fi][fj][1] + bv.y;
            float v10 = acc[fi][fj][2] + bv.x;
            float v11 = acc[fi][fj][3] + bv.y;
            const size_t i0 = (size_t)m0 * DMODEL + n;
            const size_t i1 = (size_t)(m0 + 8) * DMODEL + n;
            if (epiX) {
                // gated blend: y = 0.5*X + 0.5*sigmoid(G)*proj
                float2 x0 = *(const float2*)&epiX[i0];
                float2 x1 = *(const float2*)&epiX[i1];
                float2 g0 = *(const float2*)&epiG[i0];
                float2 g1 = *(const float2*)&epiG[i1];
                v00 = 0.5f * x0.x + 0.5f * v00 / (1.0f + __expf(-g0.x));
                v01 = 0.5f * x0.y + 0.5f * v01 / (1.0f + __expf(-g0.y));
                v10 = 0.5f * x1.x + 0.5f * v10 / (1.0f + __expf(-g1.x));
                v11 = 0.5f * x1.y + 0.5f * v11 / (1.0f + __expf(-g1.y));
            }
            if (obf) {
                __nv_bfloat16* cp = (__nv_bfloat16*)Cx;
                *(uint32_t*)&cp[i0] = pack_bf16(v00, v01);
                *(uint32_t*)&cp[i1] = pack_bf16(v10, v11);
            } else {
                float* cp = (float*)Cx;
                *(float2*)&cp[i0] = make_float2(v00, v01);
                *(float2*)&cp[i1] = make_float2(v10, v11);
            }
        }
    }
}

// ---------------------------------------------------------------------------
// Windowed attention on tensor cores (R6-proven).
// ---------------------------------------------------------------------------
#define KRANGE 192
#define NJT    24
#define ATTN_SMEM ((64 + KRANGE + KRANGE) * 128)   // 57344 B

__global__ __launch_bounds__(128)
void attn_mma(const __nv_bfloat16* __restrict__ Q,
              const __nv_bfloat16* __restrict__ K,
              const __nv_bfloat16* __restrict__ V,
              __nv_bfloat16* __restrict__ O)
{
    extern __shared__ char smem[];
    const uint32_t sQ = smem_u32(smem);
    const uint32_t sK = sQ + 64 * 128;
    const uint32_t sV = sK + KRANGE * 128;

    const int qt   = blockIdx.x;
    const int h    = blockIdx.y;
    const int b    = blockIdx.z;
    const int t    = threadIdx.x;
    const int lane = t & 31;
    const int w    = t >> 5;
    const int grp  = lane >> 2;
    const int tig  = lane & 3;

    const int q0    = qt * 64;
    const int kbase = q0 - WIN;

    const __nv_bfloat16* Qg = Q + ((size_t)b * SEQ) * DMODEL + h * HDIM;
    const __nv_bfloat16* Kg = K + ((size_t)b * SEQ) * DMODEL + h * HDIM;
    const __nv_bfloat16* Vg = V + ((size_t)b * SEQ) * DMODEL + h * HDIM;

    for (int i = t; i < 64 * 8; i += 128) {
        int row = i >> 3, c = i & 7;
        uint32_t dst = sQ + row * 128 + ((c ^ (row & 7)) << 4);
        const __nv_bfloat16* src = Qg + (size_t)(q0 + row) * DMODEL + c * 8;
        asm volatile("cp.async.cg.shared.global [%0], [%1], 16;" :: "r"(dst), "l"(src));
    }
    for (int i = t; i < KRANGE * 8; i += 128) {
        int row = i >> 3, c = i & 7;
        int jg = kbase + row;
        uint32_t off = row * 128 + ((c ^ (row & 7)) << 4);
        if ((unsigned)jg < (unsigned)SEQ) {
            const __nv_bfloat16* srck = Kg + (size_t)jg * DMODEL + c * 8;
            const __nv_bfloat16* srcv = Vg + (size_t)jg * DMODEL + c * 8;
            asm volatile("cp.async.cg.shared.global [%0], [%1], 16;" :: "r"(sK + off), "l"(srck));
            asm volatile("cp.async.cg.shared.global [%0], [%1], 16;" :: "r"(sV + off), "l"(srcv));
        } else {
            asm volatile("st.shared.v4.b32 [%0], {%1,%1,%1,%1};" :: "r"(sK + off), "r"(0u));
            asm volatile("st.shared.v4.b32 [%0], {%1,%1,%1,%1};" :: "r"(sV + off), "r"(0u));
        }
    }
    asm volatile("cp.async.commit_group;" ::: "memory");
    asm volatile("cp.async.wait_group 0;" ::: "memory");
    __syncthreads();

    const int s7 = lane & 7;
    const int m_base = w * 16;
    const uint32_t rowA = (uint32_t)((m_base + (lane & 15)) * 128);
    const int hi16 = lane >> 4;
    const uint32_t rowBoff = (uint32_t)((((lane >> 4) << 3) + (lane & 7)) * 128);
    const int cb = (lane >> 3) & 1;

    float sc[NJT][4];
    #pragma unroll
    for (int nt = 0; nt < NJT; nt++)
        #pragma unroll
        for (int r = 0; r < 4; r++)
            sc[nt][r] = 0.0f;

    #pragma unroll
    for (int ks = 0; ks < 4; ks++) {
        const uint32_t coA = (uint32_t)(((2 * ks + hi16) ^ s7) << 4);
        const uint32_t coB = (uint32_t)(((2 * ks + cb) ^ s7) << 4);
        uint32_t a0, a1, a2, a3;
        LDSM_X4(a0, a1, a2, a3, sQ + rowA + coA);
        #pragma unroll
        for (int jt = 0; jt < 12; jt++) {
            uint32_t b0, b1, b2, b3;
            LDSM_X4(b0, b1, b2, b3, sK + (uint32_t)(jt * 16 * 128) + rowBoff + coB);
            MMA_BF16(sc[2 * jt][0], sc[2 * jt][1], sc[2 * jt][2], sc[2 * jt][3],
                     a0, a1, a2, a3, b0, b1);
            MMA_BF16(sc[2 * jt + 1][0], sc[2 * jt + 1][1], sc[2 * jt + 1][2], sc[2 * jt + 1][3],
                     a0, a1, a2, a3, b2, b3);
        }
    }

    const int qi0 = q0 + m_base + grp;
    const int qi1 = qi0 + 8;
    #pragma unroll
    for (int nt = 0; nt < NJT; nt++) {
        const int jg0 = kbase + nt * 8 + tig * 2;
        const int jg1 = jg0 + 1;
        bool v00 = ((unsigned)jg0 < (unsigned)SEQ) && ((unsigned)(qi0 - jg0 + WIN) <= 2u * WIN);
        bool v01 = ((unsigned)jg1 < (unsigned)SEQ) && ((unsigned)(qi0 - jg1 + WIN) <= 2u * WIN);
        bool v10 = ((unsigned)jg0 < (unsigned)SEQ) && ((unsigned)(qi1 - jg0 + WIN) <= 2u * WIN);
        bool v11 = ((unsigned)jg1 < (unsigned)SEQ) && ((unsigned)(qi1 - jg1 + WIN) <= 2u * WIN);
        sc[nt][0] = v00 ? sc[nt][0] * SCALE : -1e30f;
        sc[nt][1] = v01 ? sc[nt][1] * SCALE : -1e30f;
        sc[nt][2] = v10 ? sc[nt][2] * SCALE : -1e30f;
        sc[nt][3] = v11 ? sc[nt][3] * SCALE : -1e30f;
    }

    float m0 = -1e30f, m1 = -1e30f;
    #pragma unroll
    for (int nt = 0; nt < NJT; nt++) {
        m0 = fmaxf(m0, fmaxf(sc[nt][0], sc[nt][1]));
        m1 = fmaxf(m1, fmaxf(sc[nt][2], sc[nt][3]));
    }
    #pragma unroll
    for (int o = 1; o <= 2; o <<= 1) {
        m0 = fmaxf(m0, __shfl_xor_sync(0xffffffffu, m0, o));
        m1 = fmaxf(m1, __shfl_xor_sync(0xffffffffu, m1, o));
    }
    float s0 = 0.0f, s1 = 0.0f;
    #pragma unroll
    for (int nt = 0; nt < NJT; nt++) {
        sc[nt][0] = __expf(sc[nt][0] - m0);
        sc[nt][1] = __expf(sc[nt][1] - m0);
        sc[nt][2] = __expf(sc[nt][2] - m1);
        sc[nt][3] = __expf(sc[nt][3] - m1);
        s0 += sc[nt][0] + sc[nt][1];
        s1 += sc[nt][2] + sc[nt][3];
    }
    #pragma unroll
    for (int o = 1; o <= 2; o <<= 1) {
        s0 += __shfl_xor_sync(0xffffffffu, s0, o);
        s1 += __shfl_xor_sync(0xffffffffu, s1, o);
    }
    const float inv0 = 1.0f / s0;
    const float inv1 = 1.0f / s1;

    float ov[8][4];
    #pragma unroll
    for (int nt = 0; nt < 8; nt++)
        #pragma unroll
        for (int r = 0; r < 4; r++)
            ov[nt][r] = 0.0f;

    const uint32_t rowV = (uint32_t)((lane & 15) * 128);
    #pragma unroll
    for (int kj = 0; kj < 12; kj++) {
        uint32_t ra0 = pack_bf16(sc[2 * kj][0] * inv0,     sc[2 * kj][1] * inv0);
        uint32_t ra1 = pack_bf16(sc[2 * kj][2] * inv1,     sc[2 * kj][3] * inv1);
        uint32_t ra2 = pack_bf16(sc[2 * kj + 1][0] * inv0, sc[2 * kj + 1][1] * inv0);
        uint32_t ra3 = pack_bf16(sc[2 * kj + 1][2] * inv1, sc[2 * kj + 1][3] * inv1);
        const uint32_t vbase = sV + (uint32_t)(kj * 16 * 128) + rowV;
        #pragma unroll
        for (int dt = 0; dt < 4; dt++) {
            const int row = kj * 16 + (lane & 15);
            const uint32_t cd = (uint32_t)(dt * 2 + (lane >> 4));
            uint32_t b0, b1, b2, b3;
            LDSM_X4_T(b0, b1, b2, b3, vbase + ((cd ^ (uint32_t)(row & 7)) << 4));
            MMA_BF16(ov[2 * dt][0], ov[2 * dt][1], ov[2 * dt][2], ov[2 * dt][3],
                     ra0, ra1, ra2, ra3, b0, b1);
            MMA_BF16(ov[2 * dt + 1][0], ov[2 * dt + 1][1], ov[2 * dt + 1][2], ov[2 * dt + 1][3],
                     ra0, ra1, ra2, ra3, b2, b3);
        }
    }

    __nv_bfloat16* O0 = O + ((size_t)b * SEQ + qi0) * DMODEL + h * HDIM;
    __nv_bfloat16* O1 = O + ((size_t)b * SEQ + qi1) * DMODEL + h * HDIM;
    #pragma unroll
    for (int nt = 0; nt < 8; nt++) {
        const int d = nt * 8 + tig * 2;
        *(uint32_t*)&O0[d] = pack_bf16(ov[nt][0], ov[nt][1]);
        *(uint32_t*)&O1[d] = pack_bf16(ov[nt][2], ov[nt][3]);
    }
}

// ---------------------------------------------------------------------------
// LayerNorm over y (gated blend already applied by the O-proj GEMM epilogue)
// ---------------------------------------------------------------------------
__global__ __launch_bounds__(256) void fused_ln(
    const float* __restrict__ Y,
    const float* __restrict__ gamma,
    const float* __restrict__ beta,
    float* __restrict__ out)
{
    const int r = blockIdx.x;
    const int t = threadIdx.x;
    const float* y = Y + (size_t)r * DMODEL;

    float v[4];
    float lsum = 0.0f, lsq = 0.0f;
    #pragma unroll
    for (int i = 0; i < 4; i++) {
        int c = t + i * 256;
        v[i] = y[c];
        lsum += v[i];
        lsq  += v[i] * v[i];
    }

    #pragma unroll
    for (int o = 16; o > 0; o >>= 1) {
        lsum += __shfl_xor_sync(0xffffffffu, lsum, o);
        lsq  += __shfl_xor_sync(0xffffffffu, lsq, o);
    }
    __shared__ float red[2][8];
    const int w = t >> 5, lane = t & 31;
    if (lane == 0) { red[0][w] = lsum; red[1][w] = lsq; }
    __syncthreads();
    float tsum = 0.0f, tsq = 0.0f;
    #pragma unroll
    for (int i = 0; i < 8; i++) { tsum += red[0][i]; tsq += red[1][i]; }

    const float mean = tsum * (1.0f / DMODEL);
    const float var  = tsq * (1.0f / DMODEL) - mean * mean;
    const float rstd = rsqrtf(var + 1e-5f);

    float* o = out + (size_t)r * DMODEL;
    #pragma unroll
    for (int i = 0; i < 4; i++) {
        int c = t + i * 256;
        o[c] = (v[i] - mean) * rstd * gamma[c] + beta[c];
    }
}

// ---------------------------------------------------------------------------
// Launch
// ---------------------------------------------------------------------------
extern "C" void kernel_launch(void* const* d_in, const int* in_sizes, int n_in,
                              void* d_out, int out_size)
{
    const float* X     = (const float*)d_in[0];
    const float* Cx    = (const float*)d_in[1];
    const float* Wq    = (const float*)d_in[2];
    const float* bq    = (const float*)d_in[3];
    const float* Wk    = (const float*)d_in[4];
    const float* bk    = (const float*)d_in[5];
    const float* Wv    = (const float*)d_in[6];
    const float* bv    = (const float*)d_in[7];
    const float* Wo    = (const float*)d_in[8];
    const float* bo    = (const float*)d_in[9];
    const float* Wg    = (const float*)d_in[10];
    const float* bg    = (const float*)d_in[11];
    const float* gamma = (const float*)d_in[12];
    const float* beta  = (const float*)d_in[13];
    float* out = (float*)d_out;

    float *g, *y;
    __nv_bfloat16 *qb, *kb, *vb, *attnb, *xb, *cxb, *wqg, *wkv, *wo;
    cudaGetSymbolAddress((void**)&g,     g_g);
    cudaGetSymbolAddress((void**)&y,     g_y);
    cudaGetSymbolAddress((void**)&qb,    g_qb);
    cudaGetSymbolAddress((void**)&kb,    g_kb);
    cudaGetSymbolAddress((void**)&vb,    g_vb);
    cudaGetSymbolAddress((void**)&attnb, g_attnb);
    cudaGetSymbolAddress((void**)&xb,    g_xb);
    cudaGetSymbolAddress((void**)&cxb,   g_cxb);
    cudaGetSymbolAddress((void**)&wqg,   g_wqg);
    cudaGetSymbolAddress((void**)&wkv,   g_wkv);
    cudaGetSymbolAddress((void**)&wo,    g_wo);

    cudaFuncSetAttribute(gemm_bf16, cudaFuncAttributeMaxDynamicSharedMemorySize, GEMM_SMEM);
    cudaFuncSetAttribute(attn_mma, cudaFuncAttributeMaxDynamicSharedMemorySize, ATTN_SMEM);

    // Fused conversions (2 launches)
    dim3 act_grid(ROWS * DMODEL / 4 / 256, 2);       // (8192, 2)
    conv_acts<<<act_grid, 256>>>((const float4*)X, (const float4*)Cx,
                                 (uint2*)xb, (uint2*)cxb);
    dim3 w_grid(DMODEL * DMODEL / 4 / 256, 5);       // (1024, 5)
    conv_weights<<<w_grid, 256>>>((const float4*)Wq, (const float4*)Wg,
                                  (const float4*)Wk, (const float4*)Wv,
                                  (const float4*)Wo,
                                  (uint2*)wqg, (uint2*)wkv, (uint2*)wo);

    // Fused projections: [Q|G] from X (q->bf16, g->f32); [K|V] from Cx (bf16)
    dim3 qg_grid(2 * DMODEL / GBN, ROWS / GBM);      // (16, 32)
    gemm_bf16<<<qg_grid, 256, GEMM_SMEM>>>(xb,  wqg, bq, bg, qb, g,  DMODEL, 1, 0,
                                           nullptr, nullptr);
    gemm_bf16<<<qg_grid, 256, GEMM_SMEM>>>(cxb, wkv, bk, bv, kb, vb, DMODEL, 1, 1,
                                           nullptr, nullptr);

    // Tensor-core windowed attention
    dim3 attn_grid(SEQ / 64, NHEAD, BATCH);          // (8, 16, 16)
    attn_mma<<<attn_grid, 128, ATTN_SMEM>>>(qb, kb, vb, attnb);

    // Output projection with fused gate+blend epilogue -> y
    dim3 o_grid(DMODEL / GBN, ROWS / GBM);           // (8, 32)
    gemm_bf16<<<o_grid, 256, GEMM_SMEM>>>(attnb, wo, bo, bo, y, y, DMODEL, 0, 0,
                                          X, g);

    // LayerNorm
    fused_ln<<<ROWS, 256>>>(y, gamma, beta, out);
}

// round 11
// speedup vs baseline: 9.4554x; 1.1769x over previous
#include <cuda_runtime.h>
#include <cuda_bf16.h>
#include <math.h>
#include <stdint.h>

// Problem constants
#define BATCH   16
#define SEQ     512
#define DMODEL  1024
#define NHEAD   16
#define HDIM    64
#define ROWS    (BATCH * SEQ)          // 8192
#define WIN     64                     // WINDOW/2
#define SCALE   0.125f                 // 64^-0.5

// ---------------------------------------------------------------------------
// Scratch (device globals: allocation-free per harness rules)
// ---------------------------------------------------------------------------
__device__ float g_g  [ROWS * DMODEL];
__device__ float g_y  [ROWS * DMODEL];
__device__ __nv_bfloat16 g_qb   [ROWS * DMODEL];
__device__ __nv_bfloat16 g_kb   [ROWS * DMODEL];
__device__ __nv_bfloat16 g_vb   [ROWS * DMODEL];
__device__ __nv_bfloat16 g_attnb[ROWS * DMODEL];
__device__ __nv_bfloat16 g_xb  [ROWS * DMODEL];
__device__ __nv_bfloat16 g_cxb [ROWS * DMODEL];
__device__ __nv_bfloat16 g_wqg [2 * DMODEL * DMODEL];   // [Wq; Wg]
__device__ __nv_bfloat16 g_wkv [2 * DMODEL * DMODEL];   // [Wk; Wv]
__device__ __nv_bfloat16 g_wo  [DMODEL * DMODEL];

// ---------------------------------------------------------------------------
// Helpers
// ---------------------------------------------------------------------------
__device__ __forceinline__ uint32_t smem_u32(const void* p) {
    uint32_t a;
    asm("{ .reg .u64 t; cvta.to.shared.u64 t, %1; cvt.u32.u64 %0, t; }"
        : "=r"(a) : "l"(p));
    return a;
}

__device__ __forceinline__ uint32_t pack_bf16(float lo, float hi) {
    __nv_bfloat162 h = __floats2bfloat162_rn(lo, hi);
    return *(uint32_t*)&h;
}

#define LDSM_X4(r0, r1, r2, r3, addr) \
    asm volatile("ldmatrix.sync.aligned.m8n8.x4.shared.b16 {%0,%1,%2,%3}, [%4];" \
                 : "=r"(r0), "=r"(r1), "=r"(r2), "=r"(r3) : "r"(addr))
#define LDSM_X4_T(r0, r1, r2, r3, addr) \
    asm volatile("ldmatrix.sync.aligned.m8n8.x4.trans.shared.b16 {%0,%1,%2,%3}, [%4];" \
                 : "=r"(r0), "=r"(r1), "=r"(r2), "=r"(r3) : "r"(addr))
#define MMA_BF16(c0, c1, c2, c3, a0, a1, a2, a3, b0, b1) \
    asm volatile("mma.sync.aligned.m16n8k16.row.col.f32.bf16.bf16.f32 " \
                 "{%0,%1,%2,%3}, {%4,%5,%6,%7}, {%8,%9}, {%0,%1,%2,%3};" \
                 : "+f"(c0), "+f"(c1), "+f"(c2), "+f"(c3) \
                 : "r"(a0), "r"(a1), "r"(a2), "r"(a3), "r"(b0), "r"(b1))

// ---------------------------------------------------------------------------
// Fused f32->bf16 conversions
// ---------------------------------------------------------------------------
__global__ __launch_bounds__(256) void conv_acts(
    const float4* __restrict__ X, const float4* __restrict__ Cx,
    uint2* __restrict__ xb, uint2* __restrict__ cxb)
{
    int i = blockIdx.x * 256 + threadIdx.x;
    const float4* src = blockIdx.y ? Cx : X;
    uint2* dst = blockIdx.y ? cxb : xb;
    float4 v = src[i];
    uint2 o;
    o.x = pack_bf16(v.x, v.y);
    o.y = pack_bf16(v.z, v.w);
    dst[i] = o;
}

__global__ __launch_bounds__(256) void conv_weights(
    const float4* __restrict__ Wq, const float4* __restrict__ Wg,
    const float4* __restrict__ Wk, const float4* __restrict__ Wv,
    const float4* __restrict__ Wo,
    uint2* __restrict__ wqg, uint2* __restrict__ wkv, uint2* __restrict__ wo)
{
    int i = blockIdx.x * 256 + threadIdx.x;
    int s = blockIdx.y;
    const float4* src = (s == 0) ? Wq : (s == 1) ? Wg : (s == 2) ? Wk
                       : (s == 3) ? Wv : Wo;
    uint2* dst = (s == 0) ? wqg
               : (s == 1) ? (wqg + DMODEL * DMODEL / 4)
               : (s == 2) ? wkv
               : (s == 3) ? (wkv + DMODEL * DMODEL / 4)
               : wo;
    float4 v = src[i];
    uint2 o;
    o.x = pack_bf16(v.x, v.y);
    o.y = pack_bf16(v.z, v.w);
    dst[i] = o;
}

// ---------------------------------------------------------------------------
// bf16 mma GEMM: CTA 128x128, BK=64, 3 stages (96KB smem), 256 thr, 2 CTA/SM.
// grid.z selects an independent (A, W, outputs) problem -> merged launches.
// Optional fused gated-blend epilogue: y = 0.5*X + 0.5*sigmoid(G)*(acc+bias)
// ---------------------------------------------------------------------------
#define GBM 128
#define GBN 128
#define GBK 64
#define GSTAGES 3
#define GITERS (DMODEL / GBK)                  // 16
#define TILE_BYTES  (GBM * GBK * 2)            // 16384
#define STAGE_BYTES (2 * TILE_BYTES)           // 32768
#define GEMM_SMEM   (GSTAGES * STAGE_BYTES)    // 98304

struct GemmPair {
    const __nv_bfloat16* A;      // [8192,1024]
    const __nv_bfloat16* W;      // [Ntot,1024]
    const float* b0;
    const float* b1;
    void* C0;
    void* C1;
    int obf0, obf1;
};
struct GemmArgs { GemmPair p[2]; };

__device__ __forceinline__ void cp_stage(uint32_t sA, uint32_t sB,
                                         const __nv_bfloat16* __restrict__ Arow,
                                         const __nv_bfloat16* __restrict__ Wrow,
                                         int k0, int t)
{
    #pragma unroll
    for (int i = 0; i < 4; i++) {
        int idx = i * 256 + t;                    // 0..1023
        int row = idx >> 3;                       // 0..127
        int c   = idx & 7;
        uint32_t soff = (uint32_t)(row * 128 + ((c ^ (row & 7)) << 4));
        const __nv_bfloat16* ga = Arow + (size_t)row * DMODEL + k0 + c * 8;
        const __nv_bfloat16* gb = Wrow + (size_t)row * DMODEL + k0 + c * 8;
        asm volatile("cp.async.cg.shared.global [%0], [%1], 16;" :: "r"(sA + soff), "l"(ga));
        asm volatile("cp.async.cg.shared.global [%0], [%1], 16;" :: "r"(sB + soff), "l"(gb));
    }
}

__global__ __launch_bounds__(256, 2)
void gemm_bf16(GemmArgs args, int nsplit,
               const float* __restrict__ epiX,
               const float* __restrict__ epiG)
{
    extern __shared__ char smem[];
    const uint32_t sb = smem_u32(smem);
    const int t = threadIdx.x;
    const int bm = blockIdx.y * GBM;
    const int bn = blockIdx.x * GBN;
    const GemmPair& P = args.p[blockIdx.z];

    const int lane = t & 31;
    const int warp = t >> 5;
    const int grp  = lane >> 2;
    const int tig  = lane & 3;
    const int wm   = warp >> 2;        // 0..1
    const int wn   = warp & 3;         // 0..3
    const int m_base = wm * 64;
    const int n_base = wn * 32;

    const bool hiHalf = (bn >= nsplit);
    void* Cx = hiHalf ? P.C1 : P.C0;
    const float* biasx = hiHalf ? P.b1 : P.b0;
    const int bnl = hiHalf ? (bn - nsplit) : bn;
    const int obf = hiHalf ? P.obf1 : P.obf0;

    const __nv_bfloat16* Arow = P.A + (size_t)bm * DMODEL;
    const __nv_bfloat16* Wrow = P.W + (size_t)bn * DMODEL;

    const int s7 = lane & 7;
    const int hi16 = lane >> 4;
    const int cb   = (lane >> 3) & 1;
    uint32_t rbA[4], rbB[2];
    #pragma unroll
    for (int fi = 0; fi < 4; fi++)
        rbA[fi] = (uint32_t)((m_base + fi * 16 + (lane & 15)) * 128);
    #pragma unroll
    for (int pr = 0; pr < 2; pr++)
        rbB[pr] = (uint32_t)((n_base + pr * 16 + ((lane >> 4) << 3) + (lane & 7)) * 128);

    float acc[4][4][4];
    #pragma unroll
    for (int fi = 0; fi < 4; fi++)
        #pragma unroll
        for (int fj = 0; fj < 4; fj++)
            #pragma unroll
            for (int r = 0; r < 4; r++)
                acc[fi][fj][r] = 0.0f;

    // Prologue: prefetch first GSTAGES-1 stages
    #pragma unroll
    for (int s = 0; s < GSTAGES - 1; s++) {
        cp_stage(sb + s * STAGE_BYTES, sb + s * STAGE_BYTES + TILE_BYTES,
                 Arow, Wrow, s * GBK, t);
        asm volatile("cp.async.commit_group;" ::: "memory");
    }

    for (int it = 0; it < GITERS; it++) {
        asm volatile("cp.async.wait_group 1;" ::: "memory");   // GSTAGES-2
        __syncthreads();

        const int ps = it + GSTAGES - 1;
        if (ps < GITERS) {
            const int s = ps % GSTAGES;
            cp_stage(sb + s * STAGE_BYTES, sb + s * STAGE_BYTES + TILE_BYTES,
                     Arow, Wrow, ps * GBK, t);
        }
        asm volatile("cp.async.commit_group;" ::: "memory");

        const uint32_t sA = sb + (it % GSTAGES) * STAGE_BYTES;
        const uint32_t sB = sA + TILE_BYTES;

        #pragma unroll
        for (int ks = 0; ks < 4; ks++) {
            const uint32_t coA = (uint32_t)(((2 * ks + hi16) ^ s7) << 4);
            const uint32_t coB = (uint32_t)(((2 * ks + cb)   ^ s7) << 4);

            uint32_t a[4][4];
            #pragma unroll
            for (int fi = 0; fi < 4; fi++)
                LDSM_X4(a[fi][0], a[fi][1], a[fi][2], a[fi][3], sA + rbA[fi] + coA);

            uint32_t b[2][4];
            #pragma unroll
            for (int pr = 0; pr < 2; pr++)
                LDSM_X4(b[pr][0], b[pr][1], b[pr][2], b[pr][3], sB + rbB[pr] + coB);

            #pragma unroll
            for (int fi = 0; fi < 4; fi++)
                #pragma unroll
                for (int fj = 0; fj < 4; fj++) {
                    const int pr = fj >> 1, hf = (fj & 1) << 1;
                    MMA_BF16(acc[fi][fj][0], acc[fi][fj][1], acc[fi][fj][2], acc[fi][fj][3],
                             a[fi][0], a[fi][1], a[fi][2], a[fi][3],
                             b[pr][hf], b[pr][hf + 1]);
                }
        }
    }

    // Epilogue
    #pragma unroll
    for (int fi = 0; fi < 4; fi++) {
        const int m0 = bm + m_base + fi * 16 + grp;
        #pragma unroll
        for (int fj = 0; fj < 4; fj++) {
            const int n = bnl + n_base + fj * 8 + tig * 2;
            const float2 bv = *(const float2*)&biasx[n];
            float v00 = acc[fi][fj][0] + bv.x;
            float v01 = acc[fi][fj][1] + bv.y;
            float v10 = acc[fi][fj][2] + bv.x;
            float v11 = acc[fi][fj][3] + bv.y;
            const size_t i0 = (size_t)m0 * DMODEL + n;
            const size_t i1 = (size_t)(m0 + 8) * DMODEL + n;
            if (epiX) {
                float2 x0 = *(const float2*)&epiX[i0];
                float2 x1 = *(const float2*)&epiX[i1];
                float2 g0 = *(const float2*)&epiG[i0];
                float2 g1 = *(const float2*)&epiG[i1];
                v00 = 0.5f * x0.x + 0.5f * v00 / (1.0f + __expf(-g0.x));
                v01 = 0.5f * x0.y + 0.5f * v01 / (1.0f + __expf(-g0.y));
                v10 = 0.5f * x1.x + 0.5f * v10 / (1.0f + __expf(-g1.x));
                v11 = 0.5f * x1.y + 0.5f * v11 / (1.0f + __expf(-g1.y));
            }
            if (obf) {
                __nv_bfloat16* cp = (__nv_bfloat16*)Cx;
                *(uint32_t*)&cp[i0] = pack_bf16(v00, v01);
                *(uint32_t*)&cp[i1] = pack_bf16(v10, v11);
            } else {
                float* cp = (float*)Cx;
                *(float2*)&cp[i0] = make_float2(v00, v01);
                *(float2*)&cp[i1] = make_float2(v10, v11);
            }
        }
    }
}

// ---------------------------------------------------------------------------
// Windowed attention on tensor cores (R6-proven).
// ---------------------------------------------------------------------------
#define KRANGE 192
#define NJT    24
#define ATTN_SMEM ((64 + KRANGE + KRANGE) * 128)   // 57344 B

__global__ __launch_bounds__(128)
void attn_mma(const __nv_bfloat16* __restrict__ Q,
              const __nv_bfloat16* __restrict__ K,
              const __nv_bfloat16* __restrict__ V,
              __nv_bfloat16* __restrict__ O)
{
    extern __shared__ char smem[];
    const uint32_t sQ = smem_u32(smem);
    const uint32_t sK = sQ + 64 * 128;
    const uint32_t sV = sK + KRANGE * 128;

    const int qt   = blockIdx.x;
    const int h    = blockIdx.y;
    const int b    = blockIdx.z;
    const int t    = threadIdx.x;
    const int lane = t & 31;
    const int w    = t >> 5;
    const int grp  = lane >> 2;
    const int tig  = lane & 3;

    const int q0    = qt * 64;
    const int kbase = q0 - WIN;

    const __nv_bfloat16* Qg = Q + ((size_t)b * SEQ) * DMODEL + h * HDIM;
    const __nv_bfloat16* Kg = K + ((size_t)b * SEQ) * DMODEL + h * HDIM;
    const __nv_bfloat16* Vg = V + ((size_t)b * SEQ) * DMODEL + h * HDIM;

    for (int i = t; i < 64 * 8; i += 128) {
        int row = i >> 3, c = i & 7;
        uint32_t dst = sQ + row * 128 + ((c ^ (row & 7)) << 4);
        const __nv_bfloat16* src = Qg + (size_t)(q0 + row) * DMODEL + c * 8;
        asm volatile("cp.async.cg.shared.global [%0], [%1], 16;" :: "r"(dst), "l"(src));
    }
    for (int i = t; i < KRANGE * 8; i += 128) {
        int row = i >> 3, c = i & 7;
        int jg = kbase + row;
        uint32_t off = row * 128 + ((c ^ (row & 7)) << 4);
        if ((unsigned)jg < (unsigned)SEQ) {
            const __nv_bfloat16* srck = Kg + (size_t)jg * DMODEL + c * 8;
            const __nv_bfloat16* srcv = Vg + (size_t)jg * DMODEL + c * 8;
            asm volatile("cp.async.cg.shared.global [%0], [%1], 16;" :: "r"(sK + off), "l"(srck));
            asm volatile("cp.async.cg.shared.global [%0], [%1], 16;" :: "r"(sV + off), "l"(srcv));
        } else {
            asm volatile("st.shared.v4.b32 [%0], {%1,%1,%1,%1};" :: "r"(sK + off), "r"(0u));
            asm volatile("st.shared.v4.b32 [%0], {%1,%1,%1,%1};" :: "r"(sV + off), "r"(0u));
        }
    }
    asm volatile("cp.async.commit_group;" ::: "memory");
    asm volatile("cp.async.wait_group 0;" ::: "memory");
    __syncthreads();

    const int s7 = lane & 7;
    const int m_base = w * 16;
    const uint32_t rowA = (uint32_t)((m_base + (lane & 15)) * 128);
    const int hi16 = lane >> 4;
    const uint32_t rowBoff = (uint32_t)((((lane >> 4) << 3) + (lane & 7)) * 128);
    const int cb = (lane >> 3) & 1;

    float sc[NJT][4];
    #pragma unroll
    for (int nt = 0; nt < NJT; nt++)
        #pragma unroll
        for (int r = 0; r < 4; r++)
            sc[nt][r] = 0.0f;

    #pragma unroll
    for (int ks = 0; ks < 4; ks++) {
        const uint32_t coA = (uint32_t)(((2 * ks + hi16) ^ s7) << 4);
        const uint32_t coB = (uint32_t)(((2 * ks + cb) ^ s7) << 4);
        uint32_t a0, a1, a2, a3;
        LDSM_X4(a0, a1, a2, a3, sQ + rowA + coA);
        #pragma unroll
        for (int jt = 0; jt < 12; jt++) {
            uint32_t b0, b1, b2, b3;
            LDSM_X4(b0, b1, b2, b3, sK + (uint32_t)(jt * 16 * 128) + rowBoff + coB);
            MMA_BF16(sc[2 * jt][0], sc[2 * jt][1], sc[2 * jt][2], sc[2 * jt][3],
                     a0, a1, a2, a3, b0, b1);
            MMA_BF16(sc[2 * jt + 1][0], sc[2 * jt + 1][1], sc[2 * jt + 1][2], sc[2 * jt + 1][3],
                     a0, a1, a2, a3, b2, b3);
        }
    }

    const int qi0 = q0 + m_base + grp;
    const int qi1 = qi0 + 8;
    #pragma unroll
    for (int nt = 0; nt < NJT; nt++) {
        const int jg0 = kbase + nt * 8 + tig * 2;
        const int jg1 = jg0 + 1;
        bool v00 = ((unsigned)jg0 < (unsigned)SEQ) && ((unsigned)(qi0 - jg0 + WIN) <= 2u * WIN);
        bool v01 = ((unsigned)jg1 < (unsigned)SEQ) && ((unsigned)(qi0 - jg1 + WIN) <= 2u * WIN);
        bool v10 = ((unsigned)jg0 < (unsigned)SEQ) && ((unsigned)(qi1 - jg0 + WIN) <= 2u * WIN);
        bool v11 = ((unsigned)jg1 < (unsigned)SEQ) && ((unsigned)(qi1 - jg1 + WIN) <= 2u * WIN);
        sc[nt][0] = v00 ? sc[nt][0] * SCALE : -1e30f;
        sc[nt][1] = v01 ? sc[nt][1] * SCALE : -1e30f;
        sc[nt][2] = v10 ? sc[nt][2] * SCALE : -1e30f;
        sc[nt][3] = v11 ? sc[nt][3] * SCALE : -1e30f;
    }

    float m0 = -1e30f, m1 = -1e30f;
    #pragma unroll
    for (int nt = 0; nt < NJT; nt++) {
        m0 = fmaxf(m0, fmaxf(sc[nt][0], sc[nt][1]));
        m1 = fmaxf(m1, fmaxf(sc[nt][2], sc[nt][3]));
    }
    #pragma unroll
    for (int o = 1; o <= 2; o <<= 1) {
        m0 = fmaxf(m0, __shfl_xor_sync(0xffffffffu, m0, o));
        m1 = fmaxf(m1, __shfl_xor_sync(0xffffffffu, m1, o));
    }
    float s0 = 0.0f, s1 = 0.0f;
    #pragma unroll
    for (int nt = 0; nt < NJT; nt++) {
        sc[nt][0] = __expf(sc[nt][0] - m0);
        sc[nt][1] = __expf(sc[nt][1] - m0);
        sc[nt][2] = __expf(sc[nt][2] - m1);
        sc[nt][3] = __expf(sc[nt][3] - m1);
        s0 += sc[nt][0] + sc[nt][1];
        s1 += sc[nt][2] + sc[nt][3];
    }
    #pragma unroll
    for (int o = 1; o <= 2; o <<= 1) {
        s0 += __shfl_xor_sync(0xffffffffu, s0, o);
        s1 += __shfl_xor_sync(0xffffffffu, s1, o);
    }
    const float inv0 = 1.0f / s0;
    const float inv1 = 1.0f / s1;

    float ov[8][4];
    #pragma unroll
    for (int nt = 0; nt < 8; nt++)
        #pragma unroll
        for (int r = 0; r < 4; r++)
            ov[nt][r] = 0.0f;

    const uint32_t rowV = (uint32_t)((lane & 15) * 128);
    #pragma unroll
    for (int kj = 0; kj < 12; kj++) {
        uint32_t ra0 = pack_bf16(sc[2 * kj][0] * inv0,     sc[2 * kj][1] * inv0);
        uint32_t ra1 = pack_bf16(sc[2 * kj][2] * inv1,     sc[2 * kj][3] * inv1);
        uint32_t ra2 = pack_bf16(sc[2 * kj + 1][0] * inv0, sc[2 * kj + 1][1] * inv0);
        uint32_t ra3 = pack_bf16(sc[2 * kj + 1][2] * inv1, sc[2 * kj + 1][3] * inv1);
        const uint32_t vbase = sV + (uint32_t)(kj * 16 * 128) + rowV;
        #pragma unroll
        for (int dt = 0; dt < 4; dt++) {
            const int row = kj * 16 + (lane & 15);
            const uint32_t cd = (uint32_t)(dt * 2 + (lane >> 4));
            uint32_t b0, b1, b2, b3;
            LDSM_X4_T(b0, b1, b2, b3, vbase + ((cd ^ (uint32_t)(row & 7)) << 4));
            MMA_BF16(ov[2 * dt][0], ov[2 * dt][1], ov[2 * dt][2], ov[2 * dt][3],
                     ra0, ra1, ra2, ra3, b0, b1);
            MMA_BF16(ov[2 * dt + 1][0], ov[2 * dt + 1][1], ov[2 * dt + 1][2], ov[2 * dt + 1][3],
                     ra0, ra1, ra2, ra3, b2, b3);
        }
    }

    __nv_bfloat16* O0 = O + ((size_t)b * SEQ + qi0) * DMODEL + h * HDIM;
    __nv_bfloat16* O1 = O + ((size_t)b * SEQ + qi1) * DMODEL + h * HDIM;
    #pragma unroll
    for (int nt = 0; nt < 8; nt++) {
        const int d = nt * 8 + tig * 2;
        *(uint32_t*)&O0[d] = pack_bf16(ov[nt][0], ov[nt][1]);
        *(uint32_t*)&O1[d] = pack_bf16(ov[nt][2], ov[nt][3]);
    }
}

// ---------------------------------------------------------------------------
// LayerNorm over y
// ---------------------------------------------------------------------------
__global__ __launch_bounds__(256) void fused_ln(
    const float* __restrict__ Y,
    const float* __restrict__ gamma,
    const float* __restrict__ beta,
    float* __restrict__ out)
{
    const int r = blockIdx.x;
    const int t = threadIdx.x;
    const float* y = Y + (size_t)r * DMODEL;

    float v[4];
    float lsum = 0.0f, lsq = 0.0f;
    #pragma unroll
    for (int i = 0; i < 4; i++) {
        int c = t + i * 256;
        v[i] = y[c];
        lsum += v[i];
        lsq  += v[i] * v[i];
    }

    #pragma unroll
    for (int o = 16; o > 0; o >>= 1) {
        lsum += __shfl_xor_sync(0xffffffffu, lsum, o);
        lsq  += __shfl_xor_sync(0xffffffffu, lsq, o);
    }
    __shared__ float red[2][8];
    const int w = t >> 5, lane = t & 31;
    if (lane == 0) { red[0][w] = lsum; red[1][w] = lsq; }
    __syncthreads();
    float tsum = 0.0f, tsq = 0.0f;
    #pragma unroll
    for (int i = 0; i < 8; i++) { tsum += red[0][i]; tsq += red[1][i]; }

    const float mean = tsum * (1.0f / DMODEL);
    const float var  = tsq * (1.0f / DMODEL) - mean * mean;
    const float rstd = rsqrtf(var + 1e-5f);

    float* o = out + (size_t)r * DMODEL;
    #pragma unroll
    for (int i = 0; i < 4; i++) {
        int c = t + i * 256;
        o[c] = (v[i] - mean) * rstd * gamma[c] + beta[c];
    }
}

// ---------------------------------------------------------------------------
// Launch
// ---------------------------------------------------------------------------
extern "C" void kernel_launch(void* const* d_in, const int* in_sizes, int n_in,
                              void* d_out, int out_size)
{
    const float* X     = (const float*)d_in[0];
    const float* Cx    = (const float*)d_in[1];
    const float* Wq    = (const float*)d_in[2];
    const float* bq    = (const float*)d_in[3];
    const float* Wk    = (const float*)d_in[4];
    const float* bk    = (const float*)d_in[5];
    const float* Wv    = (const float*)d_in[6];
    const float* bv    = (const float*)d_in[7];
    const float* Wo    = (const float*)d_in[8];
    const float* bo    = (const float*)d_in[9];
    const float* Wg    = (const float*)d_in[10];
    const float* bg    = (const float*)d_in[11];
    const float* gamma = (const float*)d_in[12];
    const float* beta  = (const float*)d_in[13];
    float* out = (float*)d_out;

    float *g, *y;
    __nv_bfloat16 *qb, *kb, *vb, *attnb, *xb, *cxb, *wqg, *wkv, *wo;
    cudaGetSymbolAddress((void**)&g,     g_g);
    cudaGetSymbolAddress((void**)&y,     g_y);
    cudaGetSymbolAddress((void**)&qb,    g_qb);
    cudaGetSymbolAddress((void**)&kb,    g_kb);
    cudaGetSymbolAddress((void**)&vb,    g_vb);
    cudaGetSymbolAddress((void**)&attnb, g_attnb);
    cudaGetSymbolAddress((void**)&xb,    g_xb);
    cudaGetSymbolAddress((void**)&cxb,   g_cxb);
    cudaGetSymbolAddress((void**)&wqg,   g_wqg);
    cudaGetSymbolAddress((void**)&wkv,   g_wkv);
    cudaGetSymbolAddress((void**)&wo,    g_wo);

    cudaFuncSetAttribute(gemm_bf16, cudaFuncAttributeMaxDynamicSharedMemorySize, GEMM_SMEM);
    cudaFuncSetAttribute(attn_mma, cudaFuncAttributeMaxDynamicSharedMemorySize, ATTN_SMEM);

    // Fused conversions
    dim3 act_grid(ROWS * DMODEL / 4 / 256, 2);
    conv_acts<<<act_grid, 256>>>((const float4*)X, (const float4*)Cx,
                                 (uint2*)xb, (uint2*)cxb);
    dim3 w_grid(DMODEL * DMODEL / 4 / 256, 5);
    conv_weights<<<w_grid, 256>>>((const float4*)Wq, (const float4*)Wg,
                                  (const float4*)Wk, (const float4*)Wv,
                                  (const float4*)Wo,
                                  (uint2*)wqg, (uint2*)wkv, (uint2*)wo);

    // Merged fused projections: z=0 -> [Q|G] from X; z=1 -> [K|V] from Cx
    GemmArgs pa;
    pa.p[0] = { xb,  wqg, bq, bg, (void*)qb, (void*)g,  1, 0 };
    pa.p[1] = { cxb, wkv, bk, bv, (void*)kb, (void*)vb, 1, 1 };
    dim3 proj_grid(2 * DMODEL / GBN, ROWS / GBM, 2);   // (16, 64, 2)
    gemm_bf16<<<proj_grid, 256, GEMM_SMEM>>>(pa, DMODEL, nullptr, nullptr);

    // Tensor-core windowed attention
    dim3 attn_grid(SEQ / 64, NHEAD, BATCH);
    attn_mma<<<attn_grid, 128, ATTN_SMEM>>>(qb, kb, vb, attnb);

    // Output projection with fused gate+blend epilogue -> y
    GemmArgs po;
    po.p[0] = { attnb, wo, bo, bo, (void*)y, (void*)y, 0, 0 };
    po.p[1] = po.p[0];
    dim3 o_grid(DMODEL / GBN, ROWS / GBM, 1);          // (8, 64)
    gemm_bf16<<<o_grid, 256, GEMM_SMEM>>>(po, DMODEL, X, g);

    // LayerNorm
    fused_ln<<<ROWS, 256>>>(y, gamma, beta, out);
}